// round 8
// baseline (speedup 1.0000x reference)
#include <cuda_runtime.h>
#include <cstdint>

#define B_ROWS 4096
#define N_LEN  8192
#define M_FFT  4096
#define THREADS 512

#define MIN_IDX 273           // argmin |f - 40/60|  (f[i] = i*5/2048, exact fp32)
#define MAX_IDX 1707          // argmin |f - 250/60|  (band = [273, 1707) )
#define DF 0.00244140625f     // 10/4096, exact fp32

// Combined twiddle/power table (float2 entries):
//   [0,1028)     T[p]   = exp(-i*pi*p/4096), p in [0,1024] (stages + band)
//   [1028,1092)  st8    = exp(-2*pi*i*p*k/64),  p in [0,8), k in [0,8)
//   [1092,1604)  st64   = exp(-2*pi*i*p*k/512), p in [0,64), k in [0,8)
#define TAB_T    0
#define TAB_S8   1028
#define TAB_S64  1092
#define TAB_N    1608          // padded
#define TAB_BYTES (TAB_N * 8)  // 12864, multiple of 16

// smem layout (bytes from dynamic base)
#define Z_OFF    0
#define T_OFF    32768
#define MBAR_OFF (T_OFF + TAB_BYTES)    // 45632
#define SMEM_TOTAL (MBAR_OFF + 16)      // 45648

__device__ float g_losses[B_ROWS];
__device__ __align__(16) float2 g_tab[TAB_N];
__device__ unsigned int g_ctr = 0;      // last-CTA counter (self-resetting)

__global__ void twiddle_init_kernel()
{
    int p = blockIdx.x * blockDim.x + threadIdx.x;
    if (p >= TAB_N) return;
    float s = 0.0f, c = 0.0f;
    if (p < TAB_S8) {
        sincospif(-(float)p * (1.0f / 4096.0f), &s, &c);
    } else if (p < TAB_S64) {
        int idx = p - TAB_S8, pp = idx >> 3, k = idx & 7;
        sincospif(-(float)(pp * k) * (1.0f / 32.0f), &s, &c);
    } else if (p < TAB_S64 + 512) {
        int idx = p - TAB_S64, pp = idx >> 3, k = idx & 7;
        sincospif(-(float)(pp * k) * (1.0f / 256.0f), &s, &c);
    }
    g_tab[p] = make_float2(c, s);
}

__device__ __forceinline__ uint32_t smem_u32(const void* p)
{
    uint32_t a;
    asm("{ .reg .u64 t; cvta.to.shared.u64 t, %1; cvt.u32.u64 %0, t; }"
        : "=r"(a) : "l"(p));
    return a;
}

// GF(2)-linear swizzle on float2 indices (conflict-free for all stage
// patterns; validated R5-R7, rel_err 0).
__host__ __device__ constexpr int Sc(int i)
{
    return i ^ ((i >> 6) & 1) ^ ((i >> 5) & 0xC) ^ ((i >> 8) & 0xE);
}

__device__ __forceinline__ void cmul(float ar, float ai, float br, float bi,
                                     float& cr, float& ci)
{
    cr = ar * br - ai * bi;
    ci = ar * bi + ai * br;
}

// 8-point DFT (DIT), natural order, in-place on register arrays.
__device__ __forceinline__ void dft8(float* xr, float* xi)
{
    const float C = 0.70710678118654752f;
    float t0r = xr[0] + xr[4], t0i = xi[0] + xi[4];
    float t1r = xr[0] - xr[4], t1i = xi[0] - xi[4];
    float t2r = xr[2] + xr[6], t2i = xi[2] + xi[6];
    float t3r = xr[2] - xr[6], t3i = xi[2] - xi[6];
    float E0r = t0r + t2r, E0i = t0i + t2i;
    float E2r = t0r - t2r, E2i = t0i - t2i;
    float E1r = t1r + t3i, E1i = t1i - t3r;
    float E3r = t1r - t3i, E3i = t1i + t3r;
    float s0r = xr[1] + xr[5], s0i = xi[1] + xi[5];
    float s1r = xr[1] - xr[5], s1i = xi[1] - xi[5];
    float s2r = xr[3] + xr[7], s2i = xi[3] + xi[7];
    float s3r = xr[3] - xr[7], s3i = xi[3] - xi[7];
    float O0r = s0r + s2r, O0i = s0i + s2i;
    float O2r = s0r - s2r, O2i = s0i - s2i;
    float O1r = s1r + s3i, O1i = s1i - s3r;
    float O3r = s1r - s3i, O3i = s1i + s3r;
    float P1r = C * (O1r + O1i), P1i = C * (O1i - O1r);
    float P2r = O2i,             P2i = -O2r;
    float P3r = C * (O3i - O3r), P3i = -C * (O3r + O3i);
    xr[0] = E0r + O0r; xi[0] = E0i + O0i;
    xr[4] = E0r - O0r; xi[4] = E0i - O0i;
    xr[1] = E1r + P1r; xi[1] = E1i + P1i;
    xr[5] = E1r - P1r; xi[5] = E1i - P1i;
    xr[2] = E2r + P2r; xi[2] = E2i + P2i;
    xr[6] = E2r - P2r; xi[6] = E2i - P2i;
    xr[3] = E3r + P3r; xi[3] = E3i + P3i;
    xr[7] = E3r - P3r; xi[7] = E3i - P3i;
}

// Twiddle powers w^1..w^7 via depth-3 tree (used only by stage 512, where
// every thread has a distinct base twiddle).
__device__ __forceinline__ void wpowers(float w1r, float w1i, float* wr, float* wi)
{
    wr[1] = w1r; wi[1] = w1i;
    cmul(w1r, w1i, w1r, w1i, wr[2], wi[2]);
    cmul(wr[2], wi[2], w1r, w1i, wr[3], wi[3]);
    cmul(wr[2], wi[2], wr[2], wi[2], wr[4], wi[4]);
    cmul(wr[2], wi[2], wr[3], wi[3], wr[5], wi[5]);
    cmul(wr[3], wi[3], wr[3], wi[3], wr[6], wi[6]);
    cmul(wr[3], wi[3], wr[4], wi[4], wr[7], wi[7]);
}

// One radix-8 DIT stage; twiddle powers come from a precomputed table
// (broadcast / near-broadcast LDS). Butterflies partition the array per
// thread, so no sync inside the stage.
template <int L>
__device__ __forceinline__ void stage(float2* z, const float2* stab, int tid)
{
    int p, g;
    if (L == 8)       { p = tid >> 6; g = tid & 63; }
    else              { p = tid >> 3; g = tid & 7;  }   // L == 64
    const int base = g * (8 * L) + p;
    const int q0   = Sc(base);

    float xr[8], xi[8];
    {
        float2 v = z[q0];
        xr[0] = v.x; xi[0] = v.y;
    }
    #pragma unroll
    for (int k = 1; k < 8; ++k) {
        float2 v = z[q0 ^ Sc(k * L)];
        float2 w = stab[p * 8 + k];
        cmul(v.x, v.y, w.x, w.y, xr[k], xi[k]);
    }
    dft8(xr, xi);
    #pragma unroll
    for (int k = 0; k < 8; ++k)
        z[q0 ^ Sc(k * L)] = make_float2(xr[k], xi[k]);
}

__global__ void __launch_bounds__(THREADS, 3) snr_fft_kernel(
    const float* __restrict__ outputs,
    const float* __restrict__ targets,
    float* __restrict__ d_out)
{
    extern __shared__ float smem_raw[];
    char* sb = reinterpret_cast<char*>(smem_raw);
    float2* z   = reinterpret_cast<float2*>(sb + Z_OFF);   // 4096 float2
    float2* tab = reinterpret_cast<float2*>(sb + T_OFF);   // 1608 float2

    const int tid = threadIdx.x;
    const int row = blockIdx.x;
    const uint32_t mbar = smem_u32(sb + MBAR_OFF);

    // Async bulk copy of all tables (overlaps with row load + stage 1).
    if (tid == 0) {
        asm volatile("mbarrier.init.shared.b64 [%0], 1;" :: "r"(mbar) : "memory");
        asm volatile("mbarrier.arrive.expect_tx.shared.b64 _, [%0], %1;"
                     :: "r"(mbar), "r"((uint32_t)TAB_BYTES) : "memory");
        asm volatile("cp.async.bulk.shared::cluster.global.mbarrier::complete_tx::bytes "
                     "[%0], [%1], %2, [%3];"
                     :: "r"(smem_u32(tab)), "l"((const void*)g_tab),
                        "r"((uint32_t)TAB_BYTES), "r"(mbar) : "memory");
    }

    // Fused coalesced load + stage 1 (twiddle-free dft8 in registers).
    const float2* xrow = reinterpret_cast<const float2*>(outputs) + (size_t)row * M_FFT;
    {
        float xr[8], xi[8];
        #pragma unroll
        for (int k = 0; k < 8; ++k) {
            float2 v = xrow[tid + (k << 9)];
            xr[k] = v.x; xi[k] = v.y;
        }
        dft8(xr, xi);
        const int t8 = ((tid & 7) << 6) | (((tid >> 3) & 7) << 3) | (tid >> 6);
        const int q0 = Sc(t8 << 3);
        #pragma unroll
        for (int k = 0; k < 8; ++k)        // Sc(k) = k for k < 8
            z[q0 ^ k] = make_float2(xr[k], xi[k]);
    }
    __syncthreads();     // stage-1 data published; also orders mbar init

    // Wait for the tables before first use.
    asm volatile(
        "{\n\t.reg .pred P;\n"
        "WAITL%=:\n\t"
        "mbarrier.try_wait.parity.acquire.cta.shared::cta.b64 P, [%0], 0;\n\t"
        "@!P bra WAITL%=;\n\t}"
        :: "r"(mbar) : "memory");

    stage<8>(z, tab + TAB_S8, tid);
    __syncthreads();
    stage<64>(z, tab + TAB_S64, tid);
    __syncthreads();

    // Stage L=512 inlined; final Z[tid + 512c] kept in registers.
    float xr[8], xi[8];
    {
        const int q0 = Sc(tid);
        const float2 w1 = tab[TAB_T + 2 * tid];    // exp(-2*pi*i*tid/4096)
        float wr[8], wi[8];
        wpowers(w1.x, w1.y, wr, wi);
        {
            float2 v = z[q0];
            xr[0] = v.x; xi[0] = v.y;
        }
        #pragma unroll
        for (int k = 1; k < 8; ++k) {
            float2 v = z[q0 ^ Sc(k * 512)];
            cmul(v.x, v.y, wr[k], wi[k], xr[k], xi[k]);
        }
        dft8(xr, xi);
        #pragma unroll
        for (int k = 0; k < 8; ++k)
            z[q0 ^ Sc(k * 512)] = make_float2(xr[k], xi[k]);
    }
    __syncthreads();     // final Z fully published

    // r = argmin_i |f[i] - target| (first-min tie rule)
    const float tgt = targets[row];
    int ib = (int)floorf(tgt / DF) - 1;
    if (ib < 0) ib = 0;
    if (ib > M_FFT - 3) ib = M_FFT - 3;
    int r = ib;
    float best = fabsf((float)ib * DF - tgt);
    #pragma unroll
    for (int i = 1; i <= 3; ++i) {
        float d = fabsf((float)(ib + i) * DF - tgt);
        if (d < best) { best = d; r = ib + i; }
    }

    // Weight-free band sum over k in [273, 1706]; Z1 from registers.
    // Unpack twiddle folded: W(tid + 512c) = T[tid] * exp(-i*pi*c/8).
    const float2 Wt = tab[TAB_T + tid];
    const float ecr[4] = { 1.0f, 0.92387953251128675613f,
                           0.70710678118654752440f, 0.38268343236508977173f };
    const float eci[4] = { 0.0f, -0.38268343236508977173f,
                          -0.70710678118654752440f, -0.92387953251128675613f };
    float band = 0.0f;
    #pragma unroll
    for (int c = 0; c < 4; ++c) {
        int k = tid + (c << 9);
        bool valid = (c == 1) || (c == 2) ||
                     (c == 0 ? (tid >= MIN_IDX) : (k <= MAX_IDX - 1));
        if (valid) {
            float2 Z2 = z[Sc(M_FFT - k)];
            float Er = 0.5f * (xr[c] + Z2.x);
            float Ei = 0.5f * (xi[c] - Z2.y);
            float Or = 0.5f * (xi[c] + Z2.y);
            float Oi = 0.5f * (Z2.x - xr[c]);
            float Wr, Wi;
            if (c == 0) { Wr = Wt.x; Wi = Wt.y; }
            else        { cmul(Wt.x, Wt.y, ecr[c], eci[c], Wr, Wi); }
            float Xr = Er + Wr * Or - Wi * Oi;
            float Xi = Ei + Wr * Oi + Wi * Or;
            band += (Xr * Xr + Xi * Xi) * (1.0f / (float)N_LEN);
        }
    }

    // Special bins: {r-1, r, r+1, 2r-1, 2r, 2r+1}, threads 0..5.
    // Twiddle via sincospif (6 threads only).
    float spec_sig = 0.0f, spec_corr = 0.0f;
    if (tid < 6) {
        const int   joff[6] = { -1, 0, 1, -1, 0, 1 };
        const float uw[6]   = { 0.5f, 1.0f, 0.5f, 0.0f, 1.0f, 0.0f };
        const float mw[6]   = { 0.5f, 1.0f, 0.5f, 1.0f, 1.0f, 1.0f };
        int j = (tid < 3 ? r : 2 * r) + joff[tid];
        float2 Z1 = z[Sc(j)];
        float2 Z2 = z[Sc(M_FFT - j)];
        float Er = 0.5f * (Z1.x + Z2.x);
        float Ei = 0.5f * (Z1.y - Z2.y);
        float Or = 0.5f * (Z1.y + Z2.y);
        float Oi = 0.5f * (Z2.x - Z1.x);
        float Ws, Wc;
        sincospif(-(float)j * (1.0f / 4096.0f), &Ws, &Wc);
        float Xr = Er + Wc * Or - Ws * Oi;
        float Xi = Ei + Wc * Oi + Ws * Or;
        float P = (Xr * Xr + Xi * Xi) * (1.0f / (float)N_LEN);
        spec_sig  = uw[tid] * P;
        spec_corr = (j >= MIN_IDX && j < MAX_IDX) ? mw[tid] * P : 0.0f;
    }

    // Reductions.
    #pragma unroll
    for (int o = 16; o > 0; o >>= 1)
        band += __shfl_down_sync(0xffffffffu, band, o);
    #pragma unroll
    for (int o = 4; o > 0; o >>= 1) {     // lanes 0..5 live in warp 0
        spec_sig  += __shfl_down_sync(0xffffffffu, spec_sig,  o);
        spec_corr += __shfl_down_sync(0xffffffffu, spec_corr, o);
    }
    const int wid = tid >> 5, lane = tid & 31;
    float* red = reinterpret_cast<float*>(tab);   // table reads are done
    __syncthreads();
    if (lane == 0) red[wid] = band;
    if (tid == 0) { red[16] = spec_sig; red[17] = spec_corr; }
    __syncthreads();

    __shared__ bool is_last;
    if (tid == 0) {
        float Bt = 0.0f;
        #pragma unroll
        for (int i = 0; i < 16; ++i) Bt += red[i];
        float Sg = red[16];
        float Nq = Bt - red[17];
        g_losses[row] = -10.0f * log10f(Sg / (Nq + 1.0f));
        __threadfence();
        unsigned int old = atomicAdd(&g_ctr, 1u);
        is_last = (old == (unsigned int)(B_ROWS - 1));
    }
    __syncthreads();

    // Last CTA computes the mean (fixed-order, deterministic), resets ctr.
    if (is_last) {
        float s = 0.0f;
        for (int i = tid; i < B_ROWS; i += THREADS) s += g_losses[i];
        #pragma unroll
        for (int o = 16; o > 0; o >>= 1) s += __shfl_down_sync(0xffffffffu, s, o);
        __syncthreads();
        if (lane == 0) red[wid] = s;
        __syncthreads();
        if (tid == 0) {
            float t = 0.0f;
            #pragma unroll
            for (int i = 0; i < 16; ++i) t += red[i];
            d_out[0] = t * (1.0f / (float)B_ROWS);
            g_ctr = 0;
        }
    }
}

extern "C" void kernel_launch(void* const* d_in, const int* in_sizes, int n_in,
                              void* d_out, int out_size)
{
    const float* outputs = (const float*)d_in[0];   // [4096, 8192] f32
    const float* targets = (const float*)d_in[1];   // [4096, 1]    f32
    (void)in_sizes; (void)n_in; (void)out_size;

    cudaFuncSetAttribute(snr_fft_kernel,
                         cudaFuncAttributeMaxDynamicSharedMemorySize, 65536);

    twiddle_init_kernel<<<4, 512>>>();
    snr_fft_kernel<<<B_ROWS, THREADS, SMEM_TOTAL>>>(outputs, targets, (float*)d_out);
}

// round 9
// speedup vs baseline: 1.0005x; 1.0005x over previous
#include <cuda_runtime.h>
#include <cstdint>

#define B_ROWS 4096
#define N_LEN  8192
#define M_FFT  4096
#define THREADS 512

#define MIN_IDX 273           // argmin |f - 40/60|  (f[i] = i*5/2048, exact fp32)
#define MAX_IDX 1707          // argmin |f - 250/60|  (band = [273, 1707) )
#define DF 0.00244140625f     // 10/4096, exact fp32

// Twiddle table: T[p] = exp(-i*pi*p/4096), p in [0,1028); padded to 1032.
#define TAB_N    1032
#define TAB_BYTES (TAB_N * 8)           // 8256, multiple of 16

// smem layout (bytes from dynamic base)
#define Z_OFF    0
#define T_OFF    32768
#define MBAR_OFF (T_OFF + TAB_BYTES)    // 41024
#define SMEM_TOTAL (MBAR_OFF + 16)      // 41040

__device__ float g_losses[B_ROWS];
__device__ __align__(16) float2 g_tab[TAB_N];
__device__ unsigned int g_ctr = 0;      // last-CTA counter (self-resetting)

__global__ void twiddle_init_kernel()
{
    int p = blockIdx.x * blockDim.x + threadIdx.x;
    if (p < TAB_N) {
        float s, c;
        sincospif(-(float)p * (1.0f / 4096.0f), &s, &c);
        g_tab[p] = make_float2(c, s);
    }
}

__device__ __forceinline__ uint32_t smem_u32(const void* p)
{
    uint32_t a;
    asm("{ .reg .u64 t; cvta.to.shared.u64 t, %1; cvt.u32.u64 %0, t; }"
        : "=r"(a) : "l"(p));
    return a;
}

// GF(2)-linear swizzle on float2 indices (conflict-free for all stage
// patterns; validated R5-R8, rel_err 0).
__host__ __device__ constexpr int Sc(int i)
{
    return i ^ ((i >> 6) & 1) ^ ((i >> 5) & 0xC) ^ ((i >> 8) & 0xE);
}

__device__ __forceinline__ void cmul(float ar, float ai, float br, float bi,
                                     float& cr, float& ci)
{
    cr = ar * br - ai * bi;
    ci = ar * bi + ai * br;
}

// 8-point DFT (DIT), natural order, in-place on register arrays.
__device__ __forceinline__ void dft8(float* xr, float* xi)
{
    const float C = 0.70710678118654752f;
    float t0r = xr[0] + xr[4], t0i = xi[0] + xi[4];
    float t1r = xr[0] - xr[4], t1i = xi[0] - xi[4];
    float t2r = xr[2] + xr[6], t2i = xi[2] + xi[6];
    float t3r = xr[2] - xr[6], t3i = xi[2] - xi[6];
    float E0r = t0r + t2r, E0i = t0i + t2i;
    float E2r = t0r - t2r, E2i = t0i - t2i;
    float E1r = t1r + t3i, E1i = t1i - t3r;
    float E3r = t1r - t3i, E3i = t1i + t3r;
    float s0r = xr[1] + xr[5], s0i = xi[1] + xi[5];
    float s1r = xr[1] - xr[5], s1i = xi[1] - xi[5];
    float s2r = xr[3] + xr[7], s2i = xi[3] + xi[7];
    float s3r = xr[3] - xr[7], s3i = xi[3] - xi[7];
    float O0r = s0r + s2r, O0i = s0i + s2i;
    float O2r = s0r - s2r, O2i = s0i - s2i;
    float O1r = s1r + s3i, O1i = s1i - s3r;
    float O3r = s1r - s3i, O3i = s1i + s3r;
    float P1r = C * (O1r + O1i), P1i = C * (O1i - O1r);
    float P2r = O2i,             P2i = -O2r;
    float P3r = C * (O3i - O3r), P3i = -C * (O3r + O3i);
    xr[0] = E0r + O0r; xi[0] = E0i + O0i;
    xr[4] = E0r - O0r; xi[4] = E0i - O0i;
    xr[1] = E1r + P1r; xi[1] = E1i + P1i;
    xr[5] = E1r - P1r; xi[5] = E1i - P1i;
    xr[2] = E2r + P2r; xi[2] = E2i + P2i;
    xr[6] = E2r - P2r; xi[6] = E2i - P2i;
    xr[3] = E3r + P3r; xi[3] = E3i + P3i;
    xr[7] = E3r - P3r; xi[7] = E3i - P3i;
}

// Twiddle powers w^1..w^7 via depth-3 tree (pure FMA; overlaps LDS latency).
__device__ __forceinline__ void wpowers(float w1r, float w1i, float* wr, float* wi)
{
    wr[1] = w1r; wi[1] = w1i;
    cmul(w1r, w1i, w1r, w1i, wr[2], wi[2]);
    cmul(wr[2], wi[2], w1r, w1i, wr[3], wi[3]);
    cmul(wr[2], wi[2], wr[2], wi[2], wr[4], wi[4]);
    cmul(wr[2], wi[2], wr[3], wi[3], wr[5], wi[5]);
    cmul(wr[3], wi[3], wr[3], wi[3], wr[6], wi[6]);
    cmul(wr[3], wi[3], wr[4], wi[4], wr[7], wi[7]);
}

// One radix-8 DIT stage. All 8 loads issued first (MLP=8), then wpowers
// (fills the LDS latency window), then butterfly math. Per-thread
// partitioned read/write set -> no sync inside the stage.
template <int L>
__device__ __forceinline__ void stage(float2* z, const float2* T, int tid)
{
    int p, g;
    if (L == 8)       { p = tid >> 6; g = tid & 63; }
    else              { p = tid >> 3; g = tid & 7;  }   // L == 64
    const int base = g * (8 * L) + p;
    const int q0   = Sc(base);

    float2 v[8];
    v[0] = z[q0];
    #pragma unroll
    for (int k = 1; k < 8; ++k)
        v[k] = z[q0 ^ Sc(k * L)];

    const float2 w1 = T[p * (1024 / L)];   // exp(-2*pi*i*p/(8L))
    float wr[8], wi[8];
    wpowers(w1.x, w1.y, wr, wi);

    float xr[8], xi[8];
    xr[0] = v[0].x; xi[0] = v[0].y;
    #pragma unroll
    for (int k = 1; k < 8; ++k)
        cmul(v[k].x, v[k].y, wr[k], wi[k], xr[k], xi[k]);
    dft8(xr, xi);
    #pragma unroll
    for (int k = 0; k < 8; ++k)
        z[q0 ^ Sc(k * L)] = make_float2(xr[k], xi[k]);
}

__global__ void __launch_bounds__(THREADS, 3) snr_fft_kernel(
    const float* __restrict__ outputs,
    const float* __restrict__ targets,
    float* __restrict__ d_out)
{
    extern __shared__ float smem_raw[];
    char* sb = reinterpret_cast<char*>(smem_raw);
    float2* z = reinterpret_cast<float2*>(sb + Z_OFF);   // 4096 float2
    float2* T = reinterpret_cast<float2*>(sb + T_OFF);   // 1032 float2

    const int tid = threadIdx.x;
    const int row = blockIdx.x;
    const uint32_t mbar = smem_u32(sb + MBAR_OFF);

    // Async bulk copy of the twiddle table (overlaps row load + stage 1).
    if (tid == 0) {
        asm volatile("mbarrier.init.shared.b64 [%0], 1;" :: "r"(mbar) : "memory");
        asm volatile("mbarrier.arrive.expect_tx.shared.b64 _, [%0], %1;"
                     :: "r"(mbar), "r"((uint32_t)TAB_BYTES) : "memory");
        asm volatile("cp.async.bulk.shared::cluster.global.mbarrier::complete_tx::bytes "
                     "[%0], [%1], %2, [%3];"
                     :: "r"(smem_u32(T)), "l"((const void*)g_tab),
                        "r"((uint32_t)TAB_BYTES), "r"(mbar) : "memory");
    }

    // Fused coalesced load + stage 1 (twiddle-free dft8 in registers).
    const float2* xrow = reinterpret_cast<const float2*>(outputs) + (size_t)row * M_FFT;
    {
        float xr[8], xi[8];
        #pragma unroll
        for (int k = 0; k < 8; ++k) {
            float2 v = xrow[tid + (k << 9)];
            xr[k] = v.x; xi[k] = v.y;
        }
        dft8(xr, xi);
        const int t8 = ((tid & 7) << 6) | (((tid >> 3) & 7) << 3) | (tid >> 6);
        const int q0 = Sc(t8 << 3);
        #pragma unroll
        for (int k = 0; k < 8; ++k)        // Sc(k) = k for k < 8
            z[q0 ^ k] = make_float2(xr[k], xi[k]);
    }
    __syncthreads();     // stage-1 data published; also orders mbar init

    // Wait for the table before first use.
    asm volatile(
        "{\n\t.reg .pred P;\n"
        "WAITL%=:\n\t"
        "mbarrier.try_wait.parity.acquire.cta.shared::cta.b64 P, [%0], 0;\n\t"
        "@!P bra WAITL%=;\n\t}"
        :: "r"(mbar) : "memory");

    stage<8>(z, T, tid);
    __syncthreads();
    stage<64>(z, T, tid);
    __syncthreads();

    // Stage L=512 inlined; final Z[tid + 512c] kept in registers.
    float xr[8], xi[8];
    {
        const int q0 = Sc(tid);
        float2 v[8];
        v[0] = z[q0];
        #pragma unroll
        for (int k = 1; k < 8; ++k)
            v[k] = z[q0 ^ Sc(k * 512)];

        const float2 w1 = T[2 * tid];      // exp(-2*pi*i*tid/4096)
        float wr[8], wi[8];
        wpowers(w1.x, w1.y, wr, wi);

        xr[0] = v[0].x; xi[0] = v[0].y;
        #pragma unroll
        for (int k = 1; k < 8; ++k)
            cmul(v[k].x, v[k].y, wr[k], wi[k], xr[k], xi[k]);
        dft8(xr, xi);

        // Publish only the index range the epilogue reads: [272, 3824].
        const int q0w = q0;
        #pragma unroll
        for (int k = 0; k < 8; ++k) {
            bool need = (k == 0) ? (tid >= 272)
                      : (k == 7) ? (tid <= 240)
                      : true;
            if (need)
                z[q0w ^ Sc(k * 512)] = make_float2(xr[k], xi[k]);
        }
    }
    __syncthreads();     // final Z published

    // r = argmin_i |f[i] - target| (first-min tie rule)
    const float tgt = targets[row];
    int ib = (int)floorf(tgt / DF) - 1;
    if (ib < 0) ib = 0;
    if (ib > M_FFT - 3) ib = M_FFT - 3;
    int r = ib;
    float best = fabsf((float)ib * DF - tgt);
    #pragma unroll
    for (int i = 1; i <= 3; ++i) {
        float d = fabsf((float)(ib + i) * DF - tgt);
        if (d < best) { best = d; r = ib + i; }
    }

    // Weight-free band sum over k in [273, 1706]; Z1 from registers.
    // Unpack twiddle folded: W(tid + 512c) = T[tid] * exp(-i*pi*c/8).
    const float2 Wt = T[tid];
    const float ecr[4] = { 1.0f, 0.92387953251128675613f,
                           0.70710678118654752440f, 0.38268343236508977173f };
    const float eci[4] = { 0.0f, -0.38268343236508977173f,
                          -0.70710678118654752440f, -0.92387953251128675613f };
    float band = 0.0f;
    #pragma unroll
    for (int c = 0; c < 4; ++c) {
        int k = tid + (c << 9);
        bool valid = (c == 1) || (c == 2) ||
                     (c == 0 ? (tid >= MIN_IDX) : (k <= MAX_IDX - 1));
        if (valid) {
            float2 Z2 = z[Sc(M_FFT - k)];
            float Er = 0.5f * (xr[c] + Z2.x);
            float Ei = 0.5f * (xi[c] - Z2.y);
            float Or = 0.5f * (xi[c] + Z2.y);
            float Oi = 0.5f * (Z2.x - xr[c]);
            float Wr, Wi;
            if (c == 0) { Wr = Wt.x; Wi = Wt.y; }
            else        { cmul(Wt.x, Wt.y, ecr[c], eci[c], Wr, Wi); }
            float Xr = Er + Wr * Or - Wi * Oi;
            float Xi = Ei + Wr * Oi + Wi * Or;
            band += (Xr * Xr + Xi * Xi) * (1.0f / (float)N_LEN);
        }
    }

    // Special bins: {r-1, r, r+1, 2r-1, 2r, 2r+1}, threads 0..5.
    float spec_sig = 0.0f, spec_corr = 0.0f;
    if (tid < 6) {
        const int   joff[6] = { -1, 0, 1, -1, 0, 1 };
        const float uw[6]   = { 0.5f, 1.0f, 0.5f, 0.0f, 1.0f, 0.0f };
        const float mw[6]   = { 0.5f, 1.0f, 0.5f, 1.0f, 1.0f, 1.0f };
        int j = (tid < 3 ? r : 2 * r) + joff[tid];
        float2 Z1 = z[Sc(j)];
        float2 Z2 = z[Sc(M_FFT - j)];
        float Er = 0.5f * (Z1.x + Z2.x);
        float Ei = 0.5f * (Z1.y - Z2.y);
        float Or = 0.5f * (Z1.y + Z2.y);
        float Oi = 0.5f * (Z2.x - Z1.x);
        float Ws, Wc;
        sincospif(-(float)j * (1.0f / 4096.0f), &Ws, &Wc);
        float Xr = Er + Wc * Or - Ws * Oi;
        float Xi = Ei + Wc * Oi + Ws * Or;
        float P = (Xr * Xr + Xi * Xi) * (1.0f / (float)N_LEN);
        spec_sig  = uw[tid] * P;
        spec_corr = (j >= MIN_IDX && j < MAX_IDX) ? mw[tid] * P : 0.0f;
    }

    // Reductions.
    #pragma unroll
    for (int o = 16; o > 0; o >>= 1)
        band += __shfl_down_sync(0xffffffffu, band, o);
    #pragma unroll
    for (int o = 4; o > 0; o >>= 1) {     // lanes 0..5 live in warp 0
        spec_sig  += __shfl_down_sync(0xffffffffu, spec_sig,  o);
        spec_corr += __shfl_down_sync(0xffffffffu, spec_corr, o);
    }
    const int wid = tid >> 5, lane = tid & 31;
    float* red = reinterpret_cast<float*>(T);   // table reads are done
    __syncthreads();
    if (lane == 0) red[wid] = band;
    if (tid == 0) { red[16] = spec_sig; red[17] = spec_corr; }
    __syncthreads();

    __shared__ bool is_last;
    if (tid == 0) {
        float Bt = 0.0f;
        #pragma unroll
        for (int i = 0; i < 16; ++i) Bt += red[i];
        float Sg = red[16];
        float Nq = Bt - red[17];
        g_losses[row] = -10.0f * log10f(Sg / (Nq + 1.0f));
        __threadfence();
        unsigned int old = atomicAdd(&g_ctr, 1u);
        is_last = (old == (unsigned int)(B_ROWS - 1));
    }
    __syncthreads();

    // Last CTA computes the mean (fixed-order, deterministic), resets ctr.
    if (is_last) {
        float s = 0.0f;
        for (int i = tid; i < B_ROWS; i += THREADS) s += g_losses[i];
        #pragma unroll
        for (int o = 16; o > 0; o >>= 1) s += __shfl_down_sync(0xffffffffu, s, o);
        __syncthreads();
        if (lane == 0) red[wid] = s;
        __syncthreads();
        if (tid == 0) {
            float t = 0.0f;
            #pragma unroll
            for (int i = 0; i < 16; ++i) t += red[i];
            d_out[0] = t * (1.0f / (float)B_ROWS);
            g_ctr = 0;
        }
    }
}

extern "C" void kernel_launch(void* const* d_in, const int* in_sizes, int n_in,
                              void* d_out, int out_size)
{
    const float* outputs = (const float*)d_in[0];   // [4096, 8192] f32
    const float* targets = (const float*)d_in[1];   // [4096, 1]    f32
    (void)in_sizes; (void)n_in; (void)out_size;

    cudaFuncSetAttribute(snr_fft_kernel,
                         cudaFuncAttributeMaxDynamicSharedMemorySize, 65536);

    twiddle_init_kernel<<<3, 512>>>();
    snr_fft_kernel<<<B_ROWS, THREADS, SMEM_TOTAL>>>(outputs, targets, (float*)d_out);
}

// round 10
// speedup vs baseline: 1.0035x; 1.0030x over previous
#include <cuda_runtime.h>
#include <cstdint>

#define B_ROWS 4096
#define N_LEN  8192
#define M_FFT  4096
#define THREADS 512

#define MIN_IDX 273           // argmin |f - 40/60|  (f[i] = i*5/2048, exact fp32)
#define MAX_IDX 1707          // argmin |f - 250/60|  (band = [273, 1707) )
#define DF 0.00244140625f     // 10/4096, exact fp32

// Twiddle table: T[p] = exp(-i*pi*p/4096), p in [0,1028); padded to 1032.
#define TAB_N    1032
#define TAB_BYTES (TAB_N * 8)           // 8256, multiple of 16

// smem layout (bytes from dynamic base)
#define Z_OFF    0
#define T_OFF    32768
#define MBAR_OFF (T_OFF + TAB_BYTES)    // 41024
#define SMEM_TOTAL (MBAR_OFF + 16)      // 41040

__device__ float g_losses[B_ROWS];
__device__ __align__(16) float2 g_tab[TAB_N];
__device__ unsigned int g_ctr = 0;      // last-CTA counter (self-resetting)

__global__ void twiddle_init_kernel()
{
    int p = blockIdx.x * blockDim.x + threadIdx.x;
    if (p < TAB_N) {
        float s, c;
        sincospif(-(float)p * (1.0f / 4096.0f), &s, &c);
        g_tab[p] = make_float2(c, s);
    }
}

__device__ __forceinline__ uint32_t smem_u32(const void* p)
{
    uint32_t a;
    asm("{ .reg .u64 t; cvta.to.shared.u64 t, %1; cvt.u32.u64 %0, t; }"
        : "=r"(a) : "l"(p));
    return a;
}

// GF(2)-linear swizzle on float2 indices (conflict-free for all stage
// patterns; validated R5-R9, rel_err 0).
__host__ __device__ constexpr int Sc(int i)
{
    return i ^ ((i >> 6) & 1) ^ ((i >> 5) & 0xC) ^ ((i >> 8) & 0xE);
}

// ---------- packed f32x2 complex helpers (Blackwell FFMA2 path) ----------
typedef unsigned long long c64;      // (real, imag) packed as 2 x f32

__device__ __forceinline__ c64 pk(float lo, float hi)
{
    c64 r;
    asm("mov.b64 %0, {%1, %2};" : "=l"(r) : "f"(lo), "f"(hi));
    return r;
}
__device__ __forceinline__ float lof(c64 a)
{
    float f;
    asm("{ .reg .f32 h; mov.b64 {%0, h}, %1; }" : "=f"(f) : "l"(a));
    return f;
}
__device__ __forceinline__ float hif(c64 a)
{
    float f;
    asm("{ .reg .f32 l; mov.b64 {l, %0}, %1; }" : "=f"(f) : "l"(a));
    return f;
}
__device__ __forceinline__ c64 addc(c64 a, c64 b)
{
    c64 r;
    asm("add.rn.f32x2 %0, %1, %2;" : "=l"(r) : "l"(a), "l"(b));
    return r;
}
// a - b  ==  fma(b, (-1,-1), a)
__device__ __forceinline__ c64 subc(c64 a, c64 b, c64 NEG1)
{
    c64 r;
    asm("fma.rn.f32x2 %0, %1, %2, %3;" : "=l"(r) : "l"(b), "l"(NEG1), "l"(a));
    return r;
}
__device__ __forceinline__ c64 sclc(c64 a, c64 s)
{
    c64 r;
    asm("mul.rn.f32x2 %0, %1, %2;" : "=l"(r) : "l"(a), "l"(s));
    return r;
}
// multiply by -i: (r, i) -> (i, -r)
__device__ __forceinline__ c64 mni(c64 a)
{
    return pk(hif(a), -lof(a));
}
// scalar cmul producing packed result: v * (wr + i*wi)
__device__ __forceinline__ c64 cmulp(c64 v, float wr, float wi)
{
    float ar = lof(v), ai = hif(v);
    return pk(ar * wr - ai * wi, ar * wi + ai * wr);
}
__device__ __forceinline__ void cmul(float ar, float ai, float br, float bi,
                                     float& cr, float& ci)
{
    cr = ar * br - ai * bi;
    ci = ar * bi + ai * br;
}

// 8-point DFT (DIT), natural order, in-place, packed f32x2 arithmetic.
__device__ __forceinline__ void dft8p(c64* x, c64 NEG1, c64 CC)
{
    c64 t0 = addc(x[0], x[4]), t1 = subc(x[0], x[4], NEG1);
    c64 t2 = addc(x[2], x[6]), t3 = subc(x[2], x[6], NEG1);
    c64 E0 = addc(t0, t2),     E2 = subc(t0, t2, NEG1);
    c64 mt3 = mni(t3);
    c64 E1 = addc(t1, mt3),    E3 = subc(t1, mt3, NEG1);
    c64 s0 = addc(x[1], x[5]), s1 = subc(x[1], x[5], NEG1);
    c64 s2 = addc(x[3], x[7]), s3 = subc(x[3], x[7], NEG1);
    c64 O0 = addc(s0, s2),     O2 = subc(s0, s2, NEG1);
    c64 ms3 = mni(s3);
    c64 O1 = addc(s1, ms3),    O3 = subc(s1, ms3, NEG1);
    c64 P1 = sclc(addc(O1, mni(O1)), CC);
    c64 P2 = mni(O2);
    c64 P3 = sclc(subc(mni(O3), O3, NEG1), CC);
    x[0] = addc(E0, O0); x[4] = subc(E0, O0, NEG1);
    x[1] = addc(E1, P1); x[5] = subc(E1, P1, NEG1);
    x[2] = addc(E2, P2); x[6] = subc(E2, P2, NEG1);
    x[3] = addc(E3, P3); x[7] = subc(E3, P3, NEG1);
}

// Twiddle powers w^1..w^7 via depth-3 tree (scalar FMA; overlaps LDS latency).
__device__ __forceinline__ void wpowers(float w1r, float w1i, float* wr, float* wi)
{
    wr[1] = w1r; wi[1] = w1i;
    cmul(w1r, w1i, w1r, w1i, wr[2], wi[2]);
    cmul(wr[2], wi[2], w1r, w1i, wr[3], wi[3]);
    cmul(wr[2], wi[2], wr[2], wi[2], wr[4], wi[4]);
    cmul(wr[2], wi[2], wr[3], wi[3], wr[5], wi[5]);
    cmul(wr[3], wi[3], wr[3], wi[3], wr[6], wi[6]);
    cmul(wr[3], wi[3], wr[4], wi[4], wr[7], wi[7]);
}

// One radix-8 DIT stage, packed math. Loads first (MLP=8), wpowers fills
// the latency window. Per-thread partitioned sets -> no intra-stage sync.
template <int L>
__device__ __forceinline__ void stage(c64* zp, const float2* T, int tid,
                                      c64 NEG1, c64 CC)
{
    int p, g;
    if (L == 8)       { p = tid >> 6; g = tid & 63; }
    else              { p = tid >> 3; g = tid & 7;  }   // L == 64
    const int base = g * (8 * L) + p;
    const int q0   = Sc(base);

    c64 v[8];
    v[0] = zp[q0];
    #pragma unroll
    for (int k = 1; k < 8; ++k)
        v[k] = zp[q0 ^ Sc(k * L)];

    const float2 w1 = T[p * (1024 / L)];
    float wr[8], wi[8];
    wpowers(w1.x, w1.y, wr, wi);

    c64 x[8];
    x[0] = v[0];
    #pragma unroll
    for (int k = 1; k < 8; ++k)
        x[k] = cmulp(v[k], wr[k], wi[k]);
    dft8p(x, NEG1, CC);
    #pragma unroll
    for (int k = 0; k < 8; ++k)
        zp[q0 ^ Sc(k * L)] = x[k];
}

__global__ void __launch_bounds__(THREADS, 3) snr_fft_kernel(
    const float* __restrict__ outputs,
    const float* __restrict__ targets,
    float* __restrict__ d_out)
{
    extern __shared__ float smem_raw[];
    char* sb = reinterpret_cast<char*>(smem_raw);
    c64*    zp = reinterpret_cast<c64*>(sb + Z_OFF);     // 4096 c64
    float2* T  = reinterpret_cast<float2*>(sb + T_OFF);  // 1032 float2

    const int tid = threadIdx.x;
    const int row = blockIdx.x;
    const uint32_t mbar = smem_u32(sb + MBAR_OFF);

    const c64 NEG1 = 0xBF800000BF800000ULL;              // (-1.0f, -1.0f)
    const c64 CC   = pk(0.70710678118654752f, 0.70710678118654752f);

    // Async bulk copy of the twiddle table (overlaps row load + stage 1).
    if (tid == 0) {
        asm volatile("mbarrier.init.shared.b64 [%0], 1;" :: "r"(mbar) : "memory");
        asm volatile("mbarrier.arrive.expect_tx.shared.b64 _, [%0], %1;"
                     :: "r"(mbar), "r"((uint32_t)TAB_BYTES) : "memory");
        asm volatile("cp.async.bulk.shared::cluster.global.mbarrier::complete_tx::bytes "
                     "[%0], [%1], %2, [%3];"
                     :: "r"(smem_u32(T)), "l"((const void*)g_tab),
                        "r"((uint32_t)TAB_BYTES), "r"(mbar) : "memory");
    }

    // Fused coalesced load + stage 1 (twiddle-free packed dft8).
    const c64* xrow = reinterpret_cast<const c64*>(outputs) + (size_t)row * M_FFT;
    {
        c64 x[8];
        #pragma unroll
        for (int k = 0; k < 8; ++k)
            x[k] = xrow[tid + (k << 9)];
        dft8p(x, NEG1, CC);
        const int t8 = ((tid & 7) << 6) | (((tid >> 3) & 7) << 3) | (tid >> 6);
        const int q0 = Sc(t8 << 3);
        #pragma unroll
        for (int k = 0; k < 8; ++k)        // Sc(k) = k for k < 8
            zp[q0 ^ k] = x[k];
    }
    __syncthreads();     // stage-1 data published; also orders mbar init

    // Wait for the table before first use.
    asm volatile(
        "{\n\t.reg .pred P;\n"
        "WAITL%=:\n\t"
        "mbarrier.try_wait.parity.acquire.cta.shared::cta.b64 P, [%0], 0;\n\t"
        "@!P bra WAITL%=;\n\t}"
        :: "r"(mbar) : "memory");

    stage<8>(zp, T, tid, NEG1, CC);
    __syncthreads();
    stage<64>(zp, T, tid, NEG1, CC);
    __syncthreads();

    // Stage L=512 inlined; final Z[tid + 512c] kept in registers (packed).
    c64 x[8];
    {
        const int q0 = Sc(tid);
        c64 v[8];
        v[0] = zp[q0];
        #pragma unroll
        for (int k = 1; k < 8; ++k)
            v[k] = zp[q0 ^ Sc(k * 512)];

        const float2 w1 = T[2 * tid];      // exp(-2*pi*i*tid/4096)
        float wr[8], wi[8];
        wpowers(w1.x, w1.y, wr, wi);

        x[0] = v[0];
        #pragma unroll
        for (int k = 1; k < 8; ++k)
            x[k] = cmulp(v[k], wr[k], wi[k]);
        dft8p(x, NEG1, CC);

        // Publish only the index range the epilogue reads: [272, 3824].
        #pragma unroll
        for (int k = 0; k < 8; ++k) {
            bool need = (k == 0) ? (tid >= 272)
                      : (k == 7) ? (tid <= 240)
                      : true;
            if (need)
                zp[q0 ^ Sc(k * 512)] = x[k];
        }
    }
    __syncthreads();     // final Z published

    // r = argmin_i |f[i] - target| (first-min tie rule)
    const float tgt = targets[row];
    int ib = (int)floorf(tgt / DF) - 1;
    if (ib < 0) ib = 0;
    if (ib > M_FFT - 3) ib = M_FFT - 3;
    int r = ib;
    float best = fabsf((float)ib * DF - tgt);
    #pragma unroll
    for (int i = 1; i <= 3; ++i) {
        float d = fabsf((float)(ib + i) * DF - tgt);
        if (d < best) { best = d; r = ib + i; }
    }

    // Weight-free band sum over k in [273, 1706]; Z1 from registers.
    // Unpack twiddle folded: W(tid + 512c) = T[tid] * exp(-i*pi*c/8).
    const float2 Wt = T[tid];
    const float ecr[4] = { 1.0f, 0.92387953251128675613f,
                           0.70710678118654752440f, 0.38268343236508977173f };
    const float eci[4] = { 0.0f, -0.38268343236508977173f,
                          -0.70710678118654752440f, -0.92387953251128675613f };
    float band = 0.0f;
    #pragma unroll
    for (int c = 0; c < 4; ++c) {
        int k = tid + (c << 9);
        bool valid = (c == 1) || (c == 2) ||
                     (c == 0 ? (tid >= MIN_IDX) : (k <= MAX_IDX - 1));
        if (valid) {
            c64 Z2p = zp[Sc(M_FFT - k)];
            float Z2r = lof(Z2p), Z2i = hif(Z2p);
            float xrc = lof(x[c]), xic = hif(x[c]);
            float Er = 0.5f * (xrc + Z2r);
            float Ei = 0.5f * (xic - Z2i);
            float Or = 0.5f * (xic + Z2i);
            float Oi = 0.5f * (Z2r - xrc);
            float Wr, Wi;
            if (c == 0) { Wr = Wt.x; Wi = Wt.y; }
            else        { cmul(Wt.x, Wt.y, ecr[c], eci[c], Wr, Wi); }
            float Xr = Er + Wr * Or - Wi * Oi;
            float Xi = Ei + Wr * Oi + Wi * Or;
            band += (Xr * Xr + Xi * Xi) * (1.0f / (float)N_LEN);
        }
    }

    // Special bins: {r-1, r, r+1, 2r-1, 2r, 2r+1}, threads 0..5.
    float spec_sig = 0.0f, spec_corr = 0.0f;
    if (tid < 6) {
        const int   joff[6] = { -1, 0, 1, -1, 0, 1 };
        const float uw[6]   = { 0.5f, 1.0f, 0.5f, 0.0f, 1.0f, 0.0f };
        const float mw[6]   = { 0.5f, 1.0f, 0.5f, 1.0f, 1.0f, 1.0f };
        int j = (tid < 3 ? r : 2 * r) + joff[tid];
        c64 Z1p = zp[Sc(j)];
        c64 Z2p = zp[Sc(M_FFT - j)];
        float Z1r = lof(Z1p), Z1i = hif(Z1p);
        float Z2r = lof(Z2p), Z2i = hif(Z2p);
        float Er = 0.5f * (Z1r + Z2r);
        float Ei = 0.5f * (Z1i - Z2i);
        float Or = 0.5f * (Z1i + Z2i);
        float Oi = 0.5f * (Z2r - Z1r);
        float Ws, Wc;
        sincospif(-(float)j * (1.0f / 4096.0f), &Ws, &Wc);
        float Xr = Er + Wc * Or - Ws * Oi;
        float Xi = Ei + Wc * Oi + Ws * Or;
        float P = (Xr * Xr + Xi * Xi) * (1.0f / (float)N_LEN);
        spec_sig  = uw[tid] * P;
        spec_corr = (j >= MIN_IDX && j < MAX_IDX) ? mw[tid] * P : 0.0f;
    }

    // Reductions.
    #pragma unroll
    for (int o = 16; o > 0; o >>= 1)
        band += __shfl_down_sync(0xffffffffu, band, o);
    #pragma unroll
    for (int o = 4; o > 0; o >>= 1) {     // lanes 0..5 live in warp 0
        spec_sig  += __shfl_down_sync(0xffffffffu, spec_sig,  o);
        spec_corr += __shfl_down_sync(0xffffffffu, spec_corr, o);
    }
    const int wid = tid >> 5, lane = tid & 31;
    float* red = reinterpret_cast<float*>(T);   // table reads are done
    __syncthreads();
    if (lane == 0) red[wid] = band;
    if (tid == 0) { red[16] = spec_sig; red[17] = spec_corr; }
    __syncthreads();

    __shared__ bool is_last;
    if (tid == 0) {
        float Bt = 0.0f;
        #pragma unroll
        for (int i = 0; i < 16; ++i) Bt += red[i];
        float Sg = red[16];
        float Nq = Bt - red[17];
        g_losses[row] = -10.0f * log10f(Sg / (Nq + 1.0f));
        __threadfence();
        unsigned int old = atomicAdd(&g_ctr, 1u);
        is_last = (old == (unsigned int)(B_ROWS - 1));
    }
    __syncthreads();

    // Last CTA computes the mean (fixed-order, deterministic), resets ctr.
    if (is_last) {
        float s = 0.0f;
        for (int i = tid; i < B_ROWS; i += THREADS) s += g_losses[i];
        #pragma unroll
        for (int o = 16; o > 0; o >>= 1) s += __shfl_down_sync(0xffffffffu, s, o);
        __syncthreads();
        if (lane == 0) red[wid] = s;
        __syncthreads();
        if (tid == 0) {
            float t = 0.0f;
            #pragma unroll
            for (int i = 0; i < 16; ++i) t += red[i];
            d_out[0] = t * (1.0f / (float)B_ROWS);
            g_ctr = 0;
        }
    }
}

extern "C" void kernel_launch(void* const* d_in, const int* in_sizes, int n_in,
                              void* d_out, int out_size)
{
    const float* outputs = (const float*)d_in[0];   // [4096, 8192] f32
    const float* targets = (const float*)d_in[1];   // [4096, 1]    f32
    (void)in_sizes; (void)n_in; (void)out_size;

    cudaFuncSetAttribute(snr_fft_kernel,
                         cudaFuncAttributeMaxDynamicSharedMemorySize, 65536);

    twiddle_init_kernel<<<3, 512>>>();
    snr_fft_kernel<<<B_ROWS, THREADS, SMEM_TOTAL>>>(outputs, targets, (float*)d_out);
}

// round 11
// speedup vs baseline: 1.0331x; 1.0294x over previous
#include <cuda_runtime.h>
#include <cstdint>

#define B_ROWS 4096
#define N_LEN  8192
#define M_FFT  4096
#define THREADS 512
#define GRID_CTAS (B_ROWS / 2)

#define MIN_IDX 273           // argmin |f - 40/60|  (f[i] = i*5/2048, exact fp32)
#define MAX_IDX 1707          // argmin |f - 250/60|  (band = [273, 1707) )
#define DF 0.00244140625f     // 10/4096, exact fp32

// Twiddle table: T[p] = exp(-i*pi*p/4096), p in [0,1028); padded to 1032.
#define TAB_N    1032
#define TAB_BYTES (TAB_N * 8)           // 8256

// smem layout (bytes from dynamic base)
#define ZA_OFF   0
#define ZB_OFF   32768
#define T_OFF    65536
#define MBAR_OFF (T_OFF + TAB_BYTES)    // 73792
#define SMEM_TOTAL (MBAR_OFF + 16)      // 73808

__device__ float g_losses[B_ROWS];
__device__ __align__(16) float2 g_tab[TAB_N];
__device__ unsigned int g_ctr = 0;      // last-CTA counter (self-resetting)

__global__ void twiddle_init_kernel()
{
    int p = blockIdx.x * blockDim.x + threadIdx.x;
    if (p < TAB_N) {
        float s, c;
        sincospif(-(float)p * (1.0f / 4096.0f), &s, &c);
        g_tab[p] = make_float2(c, s);
    }
}

__device__ __forceinline__ uint32_t smem_u32(const void* p)
{
    uint32_t a;
    asm("{ .reg .u64 t; cvta.to.shared.u64 t, %1; cvt.u32.u64 %0, t; }"
        : "=r"(a) : "l"(p));
    return a;
}

// GF(2)-linear swizzle on c64 indices (conflict-free for all stage
// patterns; validated R5-R10, rel_err 0).
__host__ __device__ constexpr int Sc(int i)
{
    return i ^ ((i >> 6) & 1) ^ ((i >> 5) & 0xC) ^ ((i >> 8) & 0xE);
}

// ---------- packed f32x2 complex helpers ----------
typedef unsigned long long c64;      // (real, imag) packed as 2 x f32

__device__ __forceinline__ c64 pk(float lo, float hi)
{
    c64 r;
    asm("mov.b64 %0, {%1, %2};" : "=l"(r) : "f"(lo), "f"(hi));
    return r;
}
__device__ __forceinline__ float lof(c64 a)
{
    float f;
    asm("{ .reg .f32 h; mov.b64 {%0, h}, %1; }" : "=f"(f) : "l"(a));
    return f;
}
__device__ __forceinline__ float hif(c64 a)
{
    float f;
    asm("{ .reg .f32 l; mov.b64 {l, %0}, %1; }" : "=f"(f) : "l"(a));
    return f;
}
__device__ __forceinline__ c64 addc(c64 a, c64 b)
{
    c64 r;
    asm("add.rn.f32x2 %0, %1, %2;" : "=l"(r) : "l"(a), "l"(b));
    return r;
}
__device__ __forceinline__ c64 subc(c64 a, c64 b, c64 NEG1)
{
    c64 r;
    asm("fma.rn.f32x2 %0, %1, %2, %3;" : "=l"(r) : "l"(b), "l"(NEG1), "l"(a));
    return r;
}
__device__ __forceinline__ c64 sclc(c64 a, c64 s)
{
    c64 r;
    asm("mul.rn.f32x2 %0, %1, %2;" : "=l"(r) : "l"(a), "l"(s));
    return r;
}
// multiply by -i: (r, i) -> (i, -r)
__device__ __forceinline__ c64 mni(c64 a)
{
    return pk(hif(a), -lof(a));
}
// scalar cmul producing packed result: v * (wr + i*wi)
__device__ __forceinline__ c64 cmulp(c64 v, float wr, float wi)
{
    float ar = lof(v), ai = hif(v);
    return pk(ar * wr - ai * wi, ar * wi + ai * wr);
}
__device__ __forceinline__ void cmul(float ar, float ai, float br, float bi,
                                     float& cr, float& ci)
{
    cr = ar * br - ai * bi;
    ci = ar * bi + ai * br;
}

// 8-point DFT (DIT), natural order, in-place, packed f32x2 arithmetic.
__device__ __forceinline__ void dft8p(c64* x, c64 NEG1, c64 CC)
{
    c64 t0 = addc(x[0], x[4]), t1 = subc(x[0], x[4], NEG1);
    c64 t2 = addc(x[2], x[6]), t3 = subc(x[2], x[6], NEG1);
    c64 E0 = addc(t0, t2),     E2 = subc(t0, t2, NEG1);
    c64 mt3 = mni(t3);
    c64 E1 = addc(t1, mt3),    E3 = subc(t1, mt3, NEG1);
    c64 s0 = addc(x[1], x[5]), s1 = subc(x[1], x[5], NEG1);
    c64 s2 = addc(x[3], x[7]), s3 = subc(x[3], x[7], NEG1);
    c64 O0 = addc(s0, s2),     O2 = subc(s0, s2, NEG1);
    c64 ms3 = mni(s3);
    c64 O1 = addc(s1, ms3),    O3 = subc(s1, ms3, NEG1);
    c64 P1 = sclc(addc(O1, mni(O1)), CC);
    c64 P2 = mni(O2);
    c64 P3 = sclc(subc(mni(O3), O3, NEG1), CC);
    x[0] = addc(E0, O0); x[4] = subc(E0, O0, NEG1);
    x[1] = addc(E1, P1); x[5] = subc(E1, P1, NEG1);
    x[2] = addc(E2, P2); x[6] = subc(E2, P2, NEG1);
    x[3] = addc(E3, P3); x[7] = subc(E3, P3, NEG1);
}

// Twiddle powers w^1..w^7 via depth-3 tree (shared by both rows).
__device__ __forceinline__ void wpowers(float w1r, float w1i, float* wr, float* wi)
{
    wr[1] = w1r; wi[1] = w1i;
    cmul(w1r, w1i, w1r, w1i, wr[2], wi[2]);
    cmul(wr[2], wi[2], w1r, w1i, wr[3], wi[3]);
    cmul(wr[2], wi[2], wr[2], wi[2], wr[4], wi[4]);
    cmul(wr[2], wi[2], wr[3], wi[3], wr[5], wi[5]);
    cmul(wr[3], wi[3], wr[3], wi[3], wr[6], wi[6]);
    cmul(wr[3], wi[3], wr[4], wi[4], wr[7], wi[7]);
}

// One radix-8 DIT stage applied to TWO rows (independent dep chains; shared
// addresses + shared twiddle powers). No sync inside the stage.
template <int L>
__device__ __forceinline__ void stage2(c64* zA, c64* zB, const float2* T,
                                       int tid, c64 NEG1, c64 CC)
{
    int p, g;
    if (L == 8)       { p = tid >> 6; g = tid & 63; }
    else              { p = tid >> 3; g = tid & 7;  }   // L == 64
    const int base = g * (8 * L) + p;
    const int q0   = Sc(base);

    c64 vA[8], vB[8];
    #pragma unroll
    for (int k = 0; k < 8; ++k) {
        int q = q0 ^ Sc(k * L);
        vA[k] = zA[q];
        vB[k] = zB[q];
    }

    const float2 w1 = T[p * (1024 / L)];
    float wr[8], wi[8];
    wpowers(w1.x, w1.y, wr, wi);

    c64 xA[8], xB[8];
    xA[0] = vA[0]; xB[0] = vB[0];
    #pragma unroll
    for (int k = 1; k < 8; ++k) {
        xA[k] = cmulp(vA[k], wr[k], wi[k]);
        xB[k] = cmulp(vB[k], wr[k], wi[k]);
    }
    dft8p(xA, NEG1, CC);
    dft8p(xB, NEG1, CC);
    #pragma unroll
    for (int k = 0; k < 8; ++k) {
        int q = q0 ^ Sc(k * L);
        zA[q] = xA[k];
        zB[q] = xB[k];
    }
}

__global__ void __launch_bounds__(THREADS, 2) snr_fft_kernel(
    const float* __restrict__ outputs,
    const float* __restrict__ targets,
    float* __restrict__ d_out)
{
    extern __shared__ float smem_raw[];
    char* sb = reinterpret_cast<char*>(smem_raw);
    c64*    zA = reinterpret_cast<c64*>(sb + ZA_OFF);    // 4096 c64
    c64*    zB = reinterpret_cast<c64*>(sb + ZB_OFF);    // 4096 c64
    float2* T  = reinterpret_cast<float2*>(sb + T_OFF);  // 1032 float2

    const int tid = threadIdx.x;
    const int rowA = 2 * blockIdx.x;
    const uint32_t mbar = smem_u32(sb + MBAR_OFF);

    const c64 NEG1 = 0xBF800000BF800000ULL;              // (-1.0f, -1.0f)
    const c64 CC   = pk(0.70710678118654752f, 0.70710678118654752f);

    // Async bulk copy of the twiddle table (overlaps row loads + stage 1).
    if (tid == 0) {
        asm volatile("mbarrier.init.shared.b64 [%0], 1;" :: "r"(mbar) : "memory");
        asm volatile("mbarrier.arrive.expect_tx.shared.b64 _, [%0], %1;"
                     :: "r"(mbar), "r"((uint32_t)TAB_BYTES) : "memory");
        asm volatile("cp.async.bulk.shared::cluster.global.mbarrier::complete_tx::bytes "
                     "[%0], [%1], %2, [%3];"
                     :: "r"(smem_u32(T)), "l"((const void*)g_tab),
                        "r"((uint32_t)TAB_BYTES), "r"(mbar) : "memory");
    }

    // Fused coalesced load + stage 1 for BOTH rows (16 LDG.64, MLP=16).
    {
        const c64* xrA = reinterpret_cast<const c64*>(outputs) + (size_t)rowA * M_FFT;
        const c64* xrB = xrA + M_FFT;
        c64 a[8], b[8];
        #pragma unroll
        for (int k = 0; k < 8; ++k) {
            a[k] = xrA[tid + (k << 9)];
            b[k] = xrB[tid + (k << 9)];
        }
        dft8p(a, NEG1, CC);
        dft8p(b, NEG1, CC);
        const int t8 = ((tid & 7) << 6) | (((tid >> 3) & 7) << 3) | (tid >> 6);
        const int q0 = Sc(t8 << 3);
        #pragma unroll
        for (int k = 0; k < 8; ++k) {      // Sc(k) = k for k < 8
            zA[q0 ^ k] = a[k];
            zB[q0 ^ k] = b[k];
        }
    }
    __syncthreads();     // stage-1 data published; also orders mbar init

    // Wait for the table before first use.
    asm volatile(
        "{\n\t.reg .pred P;\n"
        "WAITL%=:\n\t"
        "mbarrier.try_wait.parity.acquire.cta.shared::cta.b64 P, [%0], 0;\n\t"
        "@!P bra WAITL%=;\n\t}"
        :: "r"(mbar) : "memory");

    stage2<8>(zA, zB, T, tid, NEG1, CC);
    __syncthreads();
    stage2<64>(zA, zB, T, tid, NEG1, CC);
    __syncthreads();

    // Stage L=512 for both rows; keep bins tid+512c (c<4) in registers.
    c64 bA[4], bB[4];
    {
        const int q0 = Sc(tid);
        const float2 w1 = T[2 * tid];      // exp(-2*pi*i*tid/4096)
        float wr[8], wi[8];
        wpowers(w1.x, w1.y, wr, wi);

        c64 x[8];
        // Row A
        x[0] = zA[q0];
        #pragma unroll
        for (int k = 1; k < 8; ++k)
            x[k] = cmulp(zA[q0 ^ Sc(k * 512)], wr[k], wi[k]);
        dft8p(x, NEG1, CC);
        #pragma unroll
        for (int k = 0; k < 8; ++k) {
            bool need = (k == 0) ? (tid >= 272)
                      : (k == 7) ? (tid <= 240)
                      : true;
            if (need) zA[q0 ^ Sc(k * 512)] = x[k];
        }
        #pragma unroll
        for (int k = 0; k < 4; ++k) bA[k] = x[k];

        // Row B
        x[0] = zB[q0];
        #pragma unroll
        for (int k = 1; k < 8; ++k)
            x[k] = cmulp(zB[q0 ^ Sc(k * 512)], wr[k], wi[k]);
        dft8p(x, NEG1, CC);
        #pragma unroll
        for (int k = 0; k < 8; ++k) {
            bool need = (k == 0) ? (tid >= 272)
                      : (k == 7) ? (tid <= 240)
                      : true;
            if (need) zB[q0 ^ Sc(k * 512)] = x[k];
        }
        #pragma unroll
        for (int k = 0; k < 4; ++k) bB[k] = x[k];
    }
    __syncthreads();     // final Z published for both rows

    // Weight-free band sums over k in [273, 1706] for both rows.
    // Unpack twiddle folded: W(tid + 512c) = T[tid] * exp(-i*pi*c/8).
    const float2 Wt = T[tid];
    const float ecr[4] = { 1.0f, 0.92387953251128675613f,
                           0.70710678118654752440f, 0.38268343236508977173f };
    const float eci[4] = { 0.0f, -0.38268343236508977173f,
                          -0.70710678118654752440f, -0.92387953251128675613f };
    float bandA = 0.0f, bandB = 0.0f;
    #pragma unroll
    for (int c = 0; c < 4; ++c) {
        int k = tid + (c << 9);
        bool valid = (c == 1) || (c == 2) ||
                     (c == 0 ? (tid >= MIN_IDX) : (k <= MAX_IDX - 1));
        if (valid) {
            float Wr, Wi;
            if (c == 0) { Wr = Wt.x; Wi = Wt.y; }
            else        { cmul(Wt.x, Wt.y, ecr[c], eci[c], Wr, Wi); }
            int q2 = Sc(M_FFT - k);
            {   // row A
                c64 Z2p = zA[q2];
                float Z2r = lof(Z2p), Z2i = hif(Z2p);
                float xrc = lof(bA[c]), xic = hif(bA[c]);
                float Er = 0.5f * (xrc + Z2r);
                float Ei = 0.5f * (xic - Z2i);
                float Or = 0.5f * (xic + Z2i);
                float Oi = 0.5f * (Z2r - xrc);
                float Xr = Er + Wr * Or - Wi * Oi;
                float Xi = Ei + Wr * Oi + Wi * Or;
                bandA += (Xr * Xr + Xi * Xi) * (1.0f / (float)N_LEN);
            }
            {   // row B
                c64 Z2p = zB[q2];
                float Z2r = lof(Z2p), Z2i = hif(Z2p);
                float xrc = lof(bB[c]), xic = hif(bB[c]);
                float Er = 0.5f * (xrc + Z2r);
                float Ei = 0.5f * (xic - Z2i);
                float Or = 0.5f * (xic + Z2i);
                float Oi = 0.5f * (Z2r - xrc);
                float Xr = Er + Wr * Or - Wi * Oi;
                float Xi = Ei + Wr * Oi + Wi * Or;
                bandB += (Xr * Xr + Xi * Xi) * (1.0f / (float)N_LEN);
            }
        }
    }

    // Special bins: threads 0..5 do row A, threads 8..13 do row B.
    float spec_sig = 0.0f, spec_corr = 0.0f;
    bool isSpec = (tid < 6) || (tid >= 8 && tid < 14);
    if (isSpec) {
        bool isB = tid >= 8;
        int s = isB ? tid - 8 : tid;
        const int   joff[6] = { -1, 0, 1, -1, 0, 1 };
        const float uw[6]   = { 0.5f, 1.0f, 0.5f, 0.0f, 1.0f, 0.0f };
        const float mw[6]   = { 0.5f, 1.0f, 0.5f, 1.0f, 1.0f, 1.0f };
        // r = argmin (first-min tie rule) for this thread's row
        const float tgt = targets[rowA + (isB ? 1 : 0)];
        int ib = (int)floorf(tgt / DF) - 1;
        if (ib < 0) ib = 0;
        if (ib > M_FFT - 3) ib = M_FFT - 3;
        int r = ib;
        float best = fabsf((float)ib * DF - tgt);
        #pragma unroll
        for (int i = 1; i <= 3; ++i) {
            float d = fabsf((float)(ib + i) * DF - tgt);
            if (d < best) { best = d; r = ib + i; }
        }
        int j = (s < 3 ? r : 2 * r) + joff[s];
        const c64* zp = isB ? zB : zA;
        c64 Z1p = zp[Sc(j)];
        c64 Z2p = zp[Sc(M_FFT - j)];
        float Z1r = lof(Z1p), Z1i = hif(Z1p);
        float Z2r = lof(Z2p), Z2i = hif(Z2p);
        float Er = 0.5f * (Z1r + Z2r);
        float Ei = 0.5f * (Z1i - Z2i);
        float Or = 0.5f * (Z1i + Z2i);
        float Oi = 0.5f * (Z2r - Z1r);
        float Ws, Wc;
        sincospif(-(float)j * (1.0f / 4096.0f), &Ws, &Wc);
        float Xr = Er + Wc * Or - Ws * Oi;
        float Xi = Ei + Wc * Oi + Ws * Or;
        float P = (Xr * Xr + Xi * Xi) * (1.0f / (float)N_LEN);
        spec_sig  = uw[s] * P;
        spec_corr = (j >= MIN_IDX && j < MAX_IDX) ? mw[s] * P : 0.0f;
    }

    // Band reductions (both rows) within warps.
    #pragma unroll
    for (int o = 16; o > 0; o >>= 1) {
        bandA += __shfl_down_sync(0xffffffffu, bandA, o);
        bandB += __shfl_down_sync(0xffffffffu, bandB, o);
    }
    const int wid = tid >> 5, lane = tid & 31;
    float* red = reinterpret_cast<float*>(T);   // T reads done after this barrier
    __syncthreads();
    if (lane == 0) { red[wid] = bandA; red[16 + wid] = bandB; }
    if (isSpec) {
        bool isB = tid >= 8;
        int s = isB ? tid - 8 : tid;
        int off = isB ? 44 : 32;
        red[off + s]     = spec_sig;
        red[off + 6 + s] = spec_corr;
    }
    __syncthreads();

    __shared__ bool is_last;
    if (tid < 2) {
        int boff = tid ? 16 : 0;
        int soff = tid ? 44 : 32;
        float Bt = 0.0f;
        #pragma unroll
        for (int i = 0; i < 16; ++i) Bt += red[boff + i];
        float Sg = 0.0f, Cr = 0.0f;
        #pragma unroll
        for (int i = 0; i < 6; ++i) { Sg += red[soff + i]; Cr += red[soff + 6 + i]; }
        g_losses[rowA + tid] = -10.0f * log10f(Sg / ((Bt - Cr) + 1.0f));
        __threadfence();
    }
    __syncthreads();
    if (tid == 0) {
        unsigned int old = atomicAdd(&g_ctr, 1u);
        is_last = (old == (unsigned int)(GRID_CTAS - 1));
    }
    __syncthreads();

    // Last CTA computes the mean (fixed-order, deterministic), resets ctr.
    if (is_last) {
        float s = 0.0f;
        for (int i = tid; i < B_ROWS; i += THREADS) s += g_losses[i];
        #pragma unroll
        for (int o = 16; o > 0; o >>= 1) s += __shfl_down_sync(0xffffffffu, s, o);
        __syncthreads();
        if (lane == 0) red[wid] = s;
        __syncthreads();
        if (tid == 0) {
            float t = 0.0f;
            #pragma unroll
            for (int i = 0; i < 16; ++i) t += red[i];
            d_out[0] = t * (1.0f / (float)B_ROWS);
            g_ctr = 0;
        }
    }
}

extern "C" void kernel_launch(void* const* d_in, const int* in_sizes, int n_in,
                              void* d_out, int out_size)
{
    const float* outputs = (const float*)d_in[0];   // [4096, 8192] f32
    const float* targets = (const float*)d_in[1];   // [4096, 1]    f32
    (void)in_sizes; (void)n_in; (void)out_size;

    cudaFuncSetAttribute(snr_fft_kernel,
                         cudaFuncAttributeMaxDynamicSharedMemorySize, SMEM_TOTAL);

    twiddle_init_kernel<<<3, 512>>>();
    snr_fft_kernel<<<GRID_CTAS, THREADS, SMEM_TOTAL>>>(outputs, targets, (float*)d_out);
}

// round 12
// speedup vs baseline: 1.0368x; 1.0036x over previous
#include <cuda_runtime.h>
#include <cstdint>

#define B_ROWS 4096
#define N_LEN  8192
#define M_FFT  4096
#define THREADS 512
#define GRID_CTAS (B_ROWS / 2)

#define MIN_IDX 273           // argmin |f - 40/60|  (f[i] = i*5/2048, exact fp32)
#define MAX_IDX 1707          // argmin |f - 250/60|  (band = [273, 1707) )
#define DF 0.00244140625f     // 10/4096, exact fp32

// Twiddle table: T[p] = exp(-i*pi*p/4096), p in [0,1028); padded to 1032.
#define TAB_N    1032
#define TAB_BYTES (TAB_N * 8)           // 8256

// smem layout (bytes from dynamic base)
#define ZA_OFF   0
#define ZB_OFF   32768
#define T_OFF    65536
#define MBAR_OFF (T_OFF + TAB_BYTES)    // 73792
#define SMEM_TOTAL (MBAR_OFF + 16)      // 73808

__device__ float g_losses[B_ROWS];
__device__ __align__(16) float2 g_tab[TAB_N];
__device__ unsigned int g_ctr = 0;      // last-CTA counter (self-resetting)

__global__ void twiddle_init_kernel()
{
    int p = blockIdx.x * blockDim.x + threadIdx.x;
    if (p < TAB_N) {
        float s, c;
        sincospif(-(float)p * (1.0f / 4096.0f), &s, &c);
        g_tab[p] = make_float2(c, s);
    }
}

__device__ __forceinline__ uint32_t smem_u32(const void* p)
{
    uint32_t a;
    asm("{ .reg .u64 t; cvta.to.shared.u64 t, %1; cvt.u32.u64 %0, t; }"
        : "=r"(a) : "l"(p));
    return a;
}

// GF(2)-linear swizzle on c64 indices (conflict-free for all stage
// patterns; validated R5-R11, rel_err 0).
__host__ __device__ constexpr int Sc(int i)
{
    return i ^ ((i >> 6) & 1) ^ ((i >> 5) & 0xC) ^ ((i >> 8) & 0xE);
}

// cos(pi*m/32) and sin(pi*m/32) literals, m in [0, 49] (used by stage<8>
// compile-time twiddles W = (C64[m], -S64[m]), m = p*k).
__device__ __constant__ const float C64c[50] = {
 1.0f, 0.99518472667219693f, 0.98078528040323044f, 0.95694033573220886f,
 0.92387953251128676f, 0.88192126434835503f, 0.83146961230254524f,
 0.77301045336273696f, 0.70710678118654752f, 0.63439328416364549f,
 0.55557023301960222f, 0.47139673682599764f, 0.38268343236508977f,
 0.29028467725446233f, 0.19509032201612827f, 0.09801714032956060f,
 0.0f, -0.09801714032956060f, -0.19509032201612827f, -0.29028467725446233f,
 -0.38268343236508977f, -0.47139673682599764f, -0.55557023301960222f,
 -0.63439328416364549f, -0.70710678118654752f, -0.77301045336273696f,
 -0.83146961230254524f, -0.88192126434835503f, -0.92387953251128676f,
 -0.95694033573220886f, -0.98078528040323044f, -0.99518472667219693f,
 -1.0f, -0.99518472667219693f, -0.98078528040323044f, -0.95694033573220886f,
 -0.92387953251128676f, -0.88192126434835503f, -0.83146961230254524f,
 -0.77301045336273696f, -0.70710678118654752f, -0.63439328416364549f,
 -0.55557023301960222f, -0.47139673682599764f, -0.38268343236508977f,
 -0.29028467725446233f, -0.19509032201612827f, -0.09801714032956060f,
 0.0f, 0.09801714032956060f };
__device__ __constant__ const float S64c[50] = {
 0.0f, 0.09801714032956060f, 0.19509032201612827f, 0.29028467725446233f,
 0.38268343236508977f, 0.47139673682599764f, 0.55557023301960222f,
 0.63439328416364549f, 0.70710678118654752f, 0.77301045336273696f,
 0.83146961230254524f, 0.88192126434835503f, 0.92387953251128676f,
 0.95694033573220886f, 0.98078528040323044f, 0.99518472667219693f,
 1.0f, 0.99518472667219693f, 0.98078528040323044f, 0.95694033573220886f,
 0.92387953251128676f, 0.88192126434835503f, 0.83146961230254524f,
 0.77301045336273696f, 0.70710678118654752f, 0.63439328416364549f,
 0.55557023301960222f, 0.47139673682599764f, 0.38268343236508977f,
 0.29028467725446233f, 0.19509032201612827f, 0.09801714032956060f,
 0.0f, -0.09801714032956060f, -0.19509032201612827f, -0.29028467725446233f,
 -0.38268343236508977f, -0.47139673682599764f, -0.55557023301960222f,
 -0.63439328416364549f, -0.70710678118654752f, -0.77301045336273696f,
 -0.83146961230254524f, -0.88192126434835503f, -0.92387953251128676f,
 -0.95694033573220886f, -0.98078528040323044f, -0.99518472667219693f,
 -1.0f, -0.99518472667219693f };

// Host-side mirrors for constexpr template folding (values identical).
#define C64L(m) (C64c[m])
#define S64L(m) (S64c[m])

// ---------- packed f32x2 complex helpers ----------
typedef unsigned long long c64;      // (real, imag) packed as 2 x f32

__device__ __forceinline__ c64 pk(float lo, float hi)
{
    c64 r;
    asm("mov.b64 %0, {%1, %2};" : "=l"(r) : "f"(lo), "f"(hi));
    return r;
}
__device__ __forceinline__ float lof(c64 a)
{
    float f;
    asm("{ .reg .f32 h; mov.b64 {%0, h}, %1; }" : "=f"(f) : "l"(a));
    return f;
}
__device__ __forceinline__ float hif(c64 a)
{
    float f;
    asm("{ .reg .f32 l; mov.b64 {l, %0}, %1; }" : "=f"(f) : "l"(a));
    return f;
}
__device__ __forceinline__ c64 addc(c64 a, c64 b)
{
    c64 r;
    asm("add.rn.f32x2 %0, %1, %2;" : "=l"(r) : "l"(a), "l"(b));
    return r;
}
__device__ __forceinline__ c64 subc(c64 a, c64 b, c64 NEG1)
{
    c64 r;
    asm("fma.rn.f32x2 %0, %1, %2, %3;" : "=l"(r) : "l"(b), "l"(NEG1), "l"(a));
    return r;
}
__device__ __forceinline__ c64 sclc(c64 a, c64 s)
{
    c64 r;
    asm("mul.rn.f32x2 %0, %1, %2;" : "=l"(r) : "l"(a), "l"(s));
    return r;
}
// multiply by -i: (r, i) -> (i, -r)
__device__ __forceinline__ c64 mni(c64 a)
{
    return pk(hif(a), -lof(a));
}
// scalar cmul producing packed result: v * (wr + i*wi)
__device__ __forceinline__ c64 cmulp(c64 v, float wr, float wi)
{
    float ar = lof(v), ai = hif(v);
    return pk(ar * wr - ai * wi, ar * wi + ai * wr);
}
__device__ __forceinline__ void cmul(float ar, float ai, float br, float bi,
                                     float& cr, float& ci)
{
    cr = ar * br - ai * bi;
    ci = ar * bi + ai * br;
}

// 8-point DFT (DIT), natural order, in-place, packed f32x2 arithmetic.
__device__ __forceinline__ void dft8p(c64* x, c64 NEG1, c64 CC)
{
    c64 t0 = addc(x[0], x[4]), t1 = subc(x[0], x[4], NEG1);
    c64 t2 = addc(x[2], x[6]), t3 = subc(x[2], x[6], NEG1);
    c64 E0 = addc(t0, t2),     E2 = subc(t0, t2, NEG1);
    c64 mt3 = mni(t3);
    c64 E1 = addc(t1, mt3),    E3 = subc(t1, mt3, NEG1);
    c64 s0 = addc(x[1], x[5]), s1 = subc(x[1], x[5], NEG1);
    c64 s2 = addc(x[3], x[7]), s3 = subc(x[3], x[7], NEG1);
    c64 O0 = addc(s0, s2),     O2 = subc(s0, s2, NEG1);
    c64 ms3 = mni(s3);
    c64 O1 = addc(s1, ms3),    O3 = subc(s1, ms3, NEG1);
    c64 P1 = sclc(addc(O1, mni(O1)), CC);
    c64 P2 = mni(O2);
    c64 P3 = sclc(subc(mni(O3), O3, NEG1), CC);
    x[0] = addc(E0, O0); x[4] = subc(E0, O0, NEG1);
    x[1] = addc(E1, P1); x[5] = subc(E1, P1, NEG1);
    x[2] = addc(E2, P2); x[6] = subc(E2, P2, NEG1);
    x[3] = addc(E3, P3); x[7] = subc(E3, P3, NEG1);
}

// Twiddle powers w^1..w^7 via depth-3 tree (shared by both rows).
__device__ __forceinline__ void wpowers(float w1r, float w1i, float* wr, float* wi)
{
    wr[1] = w1r; wi[1] = w1i;
    cmul(w1r, w1i, w1r, w1i, wr[2], wi[2]);
    cmul(wr[2], wi[2], w1r, w1i, wr[3], wi[3]);
    cmul(wr[2], wi[2], wr[2], wi[2], wr[4], wi[4]);
    cmul(wr[2], wi[2], wr[3], wi[3], wr[5], wi[5]);
    cmul(wr[3], wi[3], wr[3], wi[3], wr[6], wi[6]);
    cmul(wr[3], wi[3], wr[4], wi[4], wr[7], wi[7]);
}

// Stage<8> specialized per warp-uniform p (compile-time twiddles).
template <int P>
__device__ __forceinline__ void stage8_fixed(c64* zA, c64* zB, int tid,
                                             c64 NEG1, c64 CC)
{
    const int g    = tid & 63;
    const int base = g * 64 + P;
    const int q0   = Sc(base);

    c64 vA[8], vB[8];
    #pragma unroll
    for (int k = 0; k < 8; ++k) {
        int q = q0 ^ Sc(k * 8);
        vA[k] = zA[q];
        vB[k] = zB[q];
    }

    c64 xA[8], xB[8];
    xA[0] = vA[0]; xB[0] = vB[0];
    #pragma unroll
    for (int k = 1; k < 8; ++k) {
        if (P == 0) {
            xA[k] = vA[k];
            xB[k] = vB[k];
        } else {
            const float wr =  C64L(P * k);
            const float wi = -S64L(P * k);
            xA[k] = cmulp(vA[k], wr, wi);
            xB[k] = cmulp(vB[k], wr, wi);
        }
    }
    dft8p(xA, NEG1, CC);
    dft8p(xB, NEG1, CC);
    #pragma unroll
    for (int k = 0; k < 8; ++k) {
        int q = q0 ^ Sc(k * 8);
        zA[q] = xA[k];
        zB[q] = xB[k];
    }
}

// Stage<64>: runtime twiddles via wpowers (p varies within warp).
__device__ __forceinline__ void stage64_2(c64* zA, c64* zB, const float2* T,
                                          int tid, c64 NEG1, c64 CC)
{
    const int p = tid >> 3, g = tid & 7;
    const int base = g * 512 + p;
    const int q0   = Sc(base);

    c64 vA[8], vB[8];
    #pragma unroll
    for (int k = 0; k < 8; ++k) {
        int q = q0 ^ Sc(k * 64);
        vA[k] = zA[q];
        vB[k] = zB[q];
    }

    const float2 w1 = T[p * 16];
    float wr[8], wi[8];
    wpowers(w1.x, w1.y, wr, wi);

    c64 xA[8], xB[8];
    xA[0] = vA[0]; xB[0] = vB[0];
    #pragma unroll
    for (int k = 1; k < 8; ++k) {
        xA[k] = cmulp(vA[k], wr[k], wi[k]);
        xB[k] = cmulp(vB[k], wr[k], wi[k]);
    }
    dft8p(xA, NEG1, CC);
    dft8p(xB, NEG1, CC);
    #pragma unroll
    for (int k = 0; k < 8; ++k) {
        int q = q0 ^ Sc(k * 64);
        zA[q] = xA[k];
        zB[q] = xB[k];
    }
}

__global__ void __launch_bounds__(THREADS, 2) snr_fft_kernel(
    const float* __restrict__ outputs,
    const float* __restrict__ targets,
    float* __restrict__ d_out)
{
    extern __shared__ float smem_raw[];
    char* sb = reinterpret_cast<char*>(smem_raw);
    c64*    zA = reinterpret_cast<c64*>(sb + ZA_OFF);    // 4096 c64
    c64*    zB = reinterpret_cast<c64*>(sb + ZB_OFF);    // 4096 c64
    float2* T  = reinterpret_cast<float2*>(sb + T_OFF);  // 1032 float2

    const int tid = threadIdx.x;
    const int rowA = 2 * blockIdx.x;
    const uint32_t mbar = smem_u32(sb + MBAR_OFF);

    const c64 NEG1 = 0xBF800000BF800000ULL;              // (-1.0f, -1.0f)
    const c64 CC   = pk(0.70710678118654752f, 0.70710678118654752f);

    // Async bulk copy of the twiddle table (overlaps row loads + stage 1).
    if (tid == 0) {
        asm volatile("mbarrier.init.shared.b64 [%0], 1;" :: "r"(mbar) : "memory");
        asm volatile("mbarrier.arrive.expect_tx.shared.b64 _, [%0], %1;"
                     :: "r"(mbar), "r"((uint32_t)TAB_BYTES) : "memory");
        asm volatile("cp.async.bulk.shared::cluster.global.mbarrier::complete_tx::bytes "
                     "[%0], [%1], %2, [%3];"
                     :: "r"(smem_u32(T)), "l"((const void*)g_tab),
                        "r"((uint32_t)TAB_BYTES), "r"(mbar) : "memory");
    }

    // Fused coalesced load + stage 1 for BOTH rows (16 LDG.64, MLP=16).
    {
        const c64* xrA = reinterpret_cast<const c64*>(outputs) + (size_t)rowA * M_FFT;
        const c64* xrB = xrA + M_FFT;
        c64 a[8], b[8];
        #pragma unroll
        for (int k = 0; k < 8; ++k) {
            a[k] = xrA[tid + (k << 9)];
            b[k] = xrB[tid + (k << 9)];
        }
        dft8p(a, NEG1, CC);
        dft8p(b, NEG1, CC);
        const int t8 = ((tid & 7) << 6) | (((tid >> 3) & 7) << 3) | (tid >> 6);
        const int q0 = Sc(t8 << 3);
        #pragma unroll
        for (int k = 0; k < 8; ++k) {      // Sc(k) = k for k < 8
            zA[q0 ^ k] = a[k];
            zB[q0 ^ k] = b[k];
        }
    }
    __syncthreads();     // stage-1 data published; also orders mbar init

    // Stage <8>: warp-uniform p = tid>>6 -> compile-time twiddles.
    switch (tid >> 6) {
        case 0: stage8_fixed<0>(zA, zB, tid, NEG1, CC); break;
        case 1: stage8_fixed<1>(zA, zB, tid, NEG1, CC); break;
        case 2: stage8_fixed<2>(zA, zB, tid, NEG1, CC); break;
        case 3: stage8_fixed<3>(zA, zB, tid, NEG1, CC); break;
        case 4: stage8_fixed<4>(zA, zB, tid, NEG1, CC); break;
        case 5: stage8_fixed<5>(zA, zB, tid, NEG1, CC); break;
        case 6: stage8_fixed<6>(zA, zB, tid, NEG1, CC); break;
        default: stage8_fixed<7>(zA, zB, tid, NEG1, CC); break;
    }
    __syncthreads();

    // Wait for the table before first T use (stage<64>).
    asm volatile(
        "{\n\t.reg .pred P;\n"
        "WAITL%=:\n\t"
        "mbarrier.try_wait.parity.acquire.cta.shared::cta.b64 P, [%0], 0;\n\t"
        "@!P bra WAITL%=;\n\t}"
        :: "r"(mbar) : "memory");

    stage64_2(zA, zB, T, tid, NEG1, CC);
    __syncthreads();

    // Stage L=512: load BOTH rows first, then compute (matches stage64_2
    // pattern so row-B LDS are not serialized behind row-A STS).
    c64 bA[4], bB[4];
    {
        const int q0 = Sc(tid);
        c64 vA[8], vB[8];
        #pragma unroll
        for (int k = 0; k < 8; ++k) {
            int q = q0 ^ Sc(k * 512);
            vA[k] = zA[q];
            vB[k] = zB[q];
        }

        const float2 w1 = T[2 * tid];      // exp(-2*pi*i*tid/4096)
        float wr[8], wi[8];
        wpowers(w1.x, w1.y, wr, wi);

        c64 xA[8], xB[8];
        xA[0] = vA[0]; xB[0] = vB[0];
        #pragma unroll
        for (int k = 1; k < 8; ++k) {
            xA[k] = cmulp(vA[k], wr[k], wi[k]);
            xB[k] = cmulp(vB[k], wr[k], wi[k]);
        }
        dft8p(xA, NEG1, CC);
        dft8p(xB, NEG1, CC);

        // Publish only the index range the epilogue reads: [272, 3824].
        #pragma unroll
        for (int k = 0; k < 8; ++k) {
            bool need = (k == 0) ? (tid >= 272)
                      : (k == 7) ? (tid <= 240)
                      : true;
            if (need) {
                int q = q0 ^ Sc(k * 512);
                zA[q] = xA[k];
                zB[q] = xB[k];
            }
        }
        #pragma unroll
        for (int k = 0; k < 4; ++k) { bA[k] = xA[k]; bB[k] = xB[k]; }
    }
    __syncthreads();     // final Z published for both rows

    // Weight-free band sums over k in [273, 1706] for both rows.
    // Unpack twiddle folded: W(tid + 512c) = T[tid] * exp(-i*pi*c/8).
    const float2 Wt = T[tid];
    const float ecr[4] = { 1.0f, 0.92387953251128675613f,
                           0.70710678118654752440f, 0.38268343236508977173f };
    const float eci[4] = { 0.0f, -0.38268343236508977173f,
                          -0.70710678118654752440f, -0.92387953251128675613f };
    float bandA0 = 0.0f, bandA1 = 0.0f, bandB0 = 0.0f, bandB1 = 0.0f;
    #pragma unroll
    for (int c = 0; c < 4; ++c) {
        int k = tid + (c << 9);
        bool valid = (c == 1) || (c == 2) ||
                     (c == 0 ? (tid >= MIN_IDX) : (k <= MAX_IDX - 1));
        if (valid) {
            float Wr, Wi;
            if (c == 0) { Wr = Wt.x; Wi = Wt.y; }
            else        { cmul(Wt.x, Wt.y, ecr[c], eci[c], Wr, Wi); }
            int q2 = Sc(M_FFT - k);
            {   // row A
                c64 Z2p = zA[q2];
                float Z2r = lof(Z2p), Z2i = hif(Z2p);
                float xrc = lof(bA[c]), xic = hif(bA[c]);
                float Er = 0.5f * (xrc + Z2r);
                float Ei = 0.5f * (xic - Z2i);
                float Or = 0.5f * (xic + Z2i);
                float Oi = 0.5f * (Z2r - xrc);
                float Xr = Er + Wr * Or - Wi * Oi;
                float Xi = Ei + Wr * Oi + Wi * Or;
                float pw = (Xr * Xr + Xi * Xi) * (1.0f / (float)N_LEN);
                if (c & 1) bandA1 += pw; else bandA0 += pw;
            }
            {   // row B
                c64 Z2p = zB[q2];
                float Z2r = lof(Z2p), Z2i = hif(Z2p);
                float xrc = lof(bB[c]), xic = hif(bB[c]);
                float Er = 0.5f * (xrc + Z2r);
                float Ei = 0.5f * (xic - Z2i);
                float Or = 0.5f * (xic + Z2i);
                float Oi = 0.5f * (Z2r - xrc);
                float Xr = Er + Wr * Or - Wi * Oi;
                float Xi = Ei + Wr * Oi + Wi * Or;
                float pw = (Xr * Xr + Xi * Xi) * (1.0f / (float)N_LEN);
                if (c & 1) bandB1 += pw; else bandB0 += pw;
            }
        }
    }
    float bandA = bandA0 + bandA1;
    float bandB = bandB0 + bandB1;

    // Special bins: threads 0..5 do row A, threads 8..13 do row B.
    float spec_sig = 0.0f, spec_corr = 0.0f;
    bool isSpec = (tid < 6) || (tid >= 8 && tid < 14);
    if (isSpec) {
        bool isB = tid >= 8;
        int s = isB ? tid - 8 : tid;
        const int   joff[6] = { -1, 0, 1, -1, 0, 1 };
        const float uw[6]   = { 0.5f, 1.0f, 0.5f, 0.0f, 1.0f, 0.0f };
        const float mw[6]   = { 0.5f, 1.0f, 0.5f, 1.0f, 1.0f, 1.0f };
        const float tgt = targets[rowA + (isB ? 1 : 0)];
        int ib = (int)floorf(tgt / DF) - 1;
        if (ib < 0) ib = 0;
        if (ib > M_FFT - 3) ib = M_FFT - 3;
        int r = ib;
        float best = fabsf((float)ib * DF - tgt);
        #pragma unroll
        for (int i = 1; i <= 3; ++i) {
            float d = fabsf((float)(ib + i) * DF - tgt);
            if (d < best) { best = d; r = ib + i; }
        }
        int j = (s < 3 ? r : 2 * r) + joff[s];
        const c64* zp = isB ? zB : zA;
        c64 Z1p = zp[Sc(j)];
        c64 Z2p = zp[Sc(M_FFT - j)];
        float Z1r = lof(Z1p), Z1i = hif(Z1p);
        float Z2r = lof(Z2p), Z2i = hif(Z2p);
        float Er = 0.5f * (Z1r + Z2r);
        float Ei = 0.5f * (Z1i - Z2i);
        float Or = 0.5f * (Z1i + Z2i);
        float Oi = 0.5f * (Z2r - Z1r);
        float Ws, Wc;
        sincospif(-(float)j * (1.0f / 4096.0f), &Ws, &Wc);
        float Xr = Er + Wc * Or - Ws * Oi;
        float Xi = Ei + Wc * Oi + Ws * Or;
        float P = (Xr * Xr + Xi * Xi) * (1.0f / (float)N_LEN);
        spec_sig  = uw[s] * P;
        spec_corr = (j >= MIN_IDX && j < MAX_IDX) ? mw[s] * P : 0.0f;
    }

    // Band reductions (both rows) within warps.
    #pragma unroll
    for (int o = 16; o > 0; o >>= 1) {
        bandA += __shfl_down_sync(0xffffffffu, bandA, o);
        bandB += __shfl_down_sync(0xffffffffu, bandB, o);
    }
    const int wid = tid >> 5, lane = tid & 31;
    float* red = reinterpret_cast<float*>(T);   // T reads done after this barrier
    __syncthreads();
    if (lane == 0) { red[wid] = bandA; red[16 + wid] = bandB; }
    if (isSpec) {
        bool isB = tid >= 8;
        int s = isB ? tid - 8 : tid;
        int off = isB ? 44 : 32;
        red[off + s]     = spec_sig;
        red[off + 6 + s] = spec_corr;
    }
    __syncthreads();

    __shared__ bool is_last;
    if (tid < 2) {
        int boff = tid ? 16 : 0;
        int soff = tid ? 44 : 32;
        float Bt = 0.0f;
        #pragma unroll
        for (int i = 0; i < 16; ++i) Bt += red[boff + i];
        float Sg = 0.0f, Cr = 0.0f;
        #pragma unroll
        for (int i = 0; i < 6; ++i) { Sg += red[soff + i]; Cr += red[soff + 6 + i]; }
        g_losses[rowA + tid] = -10.0f * log10f(Sg / ((Bt - Cr) + 1.0f));
        __threadfence();
    }
    __syncthreads();
    if (tid == 0) {
        unsigned int old = atomicAdd(&g_ctr, 1u);
        is_last = (old == (unsigned int)(GRID_CTAS - 1));
    }
    __syncthreads();

    // Last CTA computes the mean (fixed-order, deterministic), resets ctr.
    if (is_last) {
        float s = 0.0f;
        for (int i = tid; i < B_ROWS; i += THREADS) s += g_losses[i];
        #pragma unroll
        for (int o = 16; o > 0; o >>= 1) s += __shfl_down_sync(0xffffffffu, s, o);
        __syncthreads();
        if (lane == 0) red[wid] = s;
        __syncthreads();
        if (tid == 0) {
            float t = 0.0f;
            #pragma unroll
            for (int i = 0; i < 16; ++i) t += red[i];
            d_out[0] = t * (1.0f / (float)B_ROWS);
            g_ctr = 0;
        }
    }
}

extern "C" void kernel_launch(void* const* d_in, const int* in_sizes, int n_in,
                              void* d_out, int out_size)
{
    const float* outputs = (const float*)d_in[0];   // [4096, 8192] f32
    const float* targets = (const float*)d_in[1];   // [4096, 1]    f32
    (void)in_sizes; (void)n_in; (void)out_size;

    cudaFuncSetAttribute(snr_fft_kernel,
                         cudaFuncAttributeMaxDynamicSharedMemorySize, SMEM_TOTAL);

    twiddle_init_kernel<<<3, 512>>>();
    snr_fft_kernel<<<GRID_CTAS, THREADS, SMEM_TOTAL>>>(outputs, targets, (float*)d_out);
}

// round 13
// speedup vs baseline: 1.0684x; 1.0304x over previous
#include <cuda_runtime.h>
#include <cstdint>

#define B_ROWS 4096
#define N_LEN  8192
#define M_FFT  4096
#define THREADS 512
#define GRID_CTAS (B_ROWS / 2)
#define WAVE_CTAS 296        // 148 SMs x 2 CTAs/SM

#define MIN_IDX 273           // argmin |f - 40/60|  (f[i] = i*5/2048, exact fp32)
#define MAX_IDX 1707          // argmin |f - 250/60|  (band = [273, 1707) )
#define DF 0.00244140625f     // 10/4096, exact fp32

// Twiddle table: T[p] = exp(-i*pi*p/4096), p in [0,1028); padded to 1032.
#define TAB_N    1032
#define TAB_BYTES (TAB_N * 8)           // 8256

// smem layout (bytes from dynamic base)
#define ZA_OFF   0
#define ZB_OFF   32768
#define T_OFF    65536
#define MBAR_OFF (T_OFF + TAB_BYTES)    // 73792
#define SMEM_TOTAL (MBAR_OFF + 16)      // 73808

__device__ float g_losses[B_ROWS];
__device__ __align__(16) float2 g_tab[TAB_N];
__device__ unsigned int g_ctr = 0;      // last-CTA counter (self-resetting)

__global__ void twiddle_init_kernel()
{
    int p = blockIdx.x * blockDim.x + threadIdx.x;
    if (p < TAB_N) {
        float s, c;
        sincospif(-(float)p * (1.0f / 4096.0f), &s, &c);
        g_tab[p] = make_float2(c, s);
    }
}

__device__ __forceinline__ uint32_t smem_u32(const void* p)
{
    uint32_t a;
    asm("{ .reg .u64 t; cvta.to.shared.u64 t, %1; cvt.u32.u64 %0, t; }"
        : "=r"(a) : "l"(p));
    return a;
}

// GF(2)-linear swizzle on c64 indices (conflict-free for all stage
// patterns; validated R5-R12, rel_err 0).
__host__ __device__ constexpr int Sc(int i)
{
    return i ^ ((i >> 6) & 1) ^ ((i >> 5) & 0xC) ^ ((i >> 8) & 0xE);
}

// cos(pi*m/32) and sin(pi*m/32) literals, m in [0, 49] (stage<8> twiddles).
__device__ __constant__ const float C64c[50] = {
 1.0f, 0.99518472667219693f, 0.98078528040323044f, 0.95694033573220886f,
 0.92387953251128676f, 0.88192126434835503f, 0.83146961230254524f,
 0.77301045336273696f, 0.70710678118654752f, 0.63439328416364549f,
 0.55557023301960222f, 0.47139673682599764f, 0.38268343236508977f,
 0.29028467725446233f, 0.19509032201612827f, 0.09801714032956060f,
 0.0f, -0.09801714032956060f, -0.19509032201612827f, -0.29028467725446233f,
 -0.38268343236508977f, -0.47139673682599764f, -0.55557023301960222f,
 -0.63439328416364549f, -0.70710678118654752f, -0.77301045336273696f,
 -0.83146961230254524f, -0.88192126434835503f, -0.92387953251128676f,
 -0.95694033573220886f, -0.98078528040323044f, -0.99518472667219693f,
 -1.0f, -0.99518472667219693f, -0.98078528040323044f, -0.95694033573220886f,
 -0.92387953251128676f, -0.88192126434835503f, -0.83146961230254524f,
 -0.77301045336273696f, -0.70710678118654752f, -0.63439328416364549f,
 -0.55557023301960222f, -0.47139673682599764f, -0.38268343236508977f,
 -0.29028467725446233f, -0.19509032201612827f, -0.09801714032956060f,
 0.0f, 0.09801714032956060f };
__device__ __constant__ const float S64c[50] = {
 0.0f, 0.09801714032956060f, 0.19509032201612827f, 0.29028467725446233f,
 0.38268343236508977f, 0.47139673682599764f, 0.55557023301960222f,
 0.63439328416364549f, 0.70710678118654752f, 0.77301045336273696f,
 0.83146961230254524f, 0.88192126434835503f, 0.92387953251128676f,
 0.95694033573220886f, 0.98078528040323044f, 0.99518472667219693f,
 1.0f, 0.99518472667219693f, 0.98078528040323044f, 0.95694033573220886f,
 0.92387953251128676f, 0.88192126434835503f, 0.83146961230254524f,
 0.77301045336273696f, 0.70710678118654752f, 0.63439328416364549f,
 0.55557023301960222f, 0.47139673682599764f, 0.38268343236508977f,
 0.29028467725446233f, 0.19509032201612827f, 0.09801714032956060f,
 0.0f, -0.09801714032956060f, -0.19509032201612827f, -0.29028467725446233f,
 -0.38268343236508977f, -0.47139673682599764f, -0.55557023301960222f,
 -0.63439328416364549f, -0.70710678118654752f, -0.77301045336273696f,
 -0.83146961230254524f, -0.88192126434835503f, -0.92387953251128676f,
 -0.95694033573220886f, -0.98078528040323044f, -0.99518472667219693f,
 -1.0f, -0.99518472667219693f };

#define C64L(m) (C64c[m])
#define S64L(m) (S64c[m])

// ---------- packed f32x2 complex helpers ----------
typedef unsigned long long c64;      // (real, imag) packed as 2 x f32

__device__ __forceinline__ c64 pk(float lo, float hi)
{
    c64 r;
    asm("mov.b64 %0, {%1, %2};" : "=l"(r) : "f"(lo), "f"(hi));
    return r;
}
__device__ __forceinline__ float lof(c64 a)
{
    float f;
    asm("{ .reg .f32 h; mov.b64 {%0, h}, %1; }" : "=f"(f) : "l"(a));
    return f;
}
__device__ __forceinline__ float hif(c64 a)
{
    float f;
    asm("{ .reg .f32 l; mov.b64 {l, %0}, %1; }" : "=f"(f) : "l"(a));
    return f;
}
__device__ __forceinline__ c64 addc(c64 a, c64 b)
{
    c64 r;
    asm("add.rn.f32x2 %0, %1, %2;" : "=l"(r) : "l"(a), "l"(b));
    return r;
}
__device__ __forceinline__ c64 subc(c64 a, c64 b, c64 NEG1)
{
    c64 r;
    asm("fma.rn.f32x2 %0, %1, %2, %3;" : "=l"(r) : "l"(b), "l"(NEG1), "l"(a));
    return r;
}
__device__ __forceinline__ c64 sclc(c64 a, c64 s)
{
    c64 r;
    asm("mul.rn.f32x2 %0, %1, %2;" : "=l"(r) : "l"(a), "l"(s));
    return r;
}
// multiply by -i: (r, i) -> (i, -r)
__device__ __forceinline__ c64 mni(c64 a)
{
    return pk(hif(a), -lof(a));
}
// scalar cmul producing packed result: v * (wr + i*wi)
__device__ __forceinline__ c64 cmulp(c64 v, float wr, float wi)
{
    float ar = lof(v), ai = hif(v);
    return pk(ar * wr - ai * wi, ar * wi + ai * wr);
}
__device__ __forceinline__ void cmul(float ar, float ai, float br, float bi,
                                     float& cr, float& ci)
{
    cr = ar * br - ai * bi;
    ci = ar * bi + ai * br;
}

// 8-point DFT (DIT), natural order, in-place, packed f32x2 arithmetic.
__device__ __forceinline__ void dft8p(c64* x, c64 NEG1, c64 CC)
{
    c64 t0 = addc(x[0], x[4]), t1 = subc(x[0], x[4], NEG1);
    c64 t2 = addc(x[2], x[6]), t3 = subc(x[2], x[6], NEG1);
    c64 E0 = addc(t0, t2),     E2 = subc(t0, t2, NEG1);
    c64 mt3 = mni(t3);
    c64 E1 = addc(t1, mt3),    E3 = subc(t1, mt3, NEG1);
    c64 s0 = addc(x[1], x[5]), s1 = subc(x[1], x[5], NEG1);
    c64 s2 = addc(x[3], x[7]), s3 = subc(x[3], x[7], NEG1);
    c64 O0 = addc(s0, s2),     O2 = subc(s0, s2, NEG1);
    c64 ms3 = mni(s3);
    c64 O1 = addc(s1, ms3),    O3 = subc(s1, ms3, NEG1);
    c64 P1 = sclc(addc(O1, mni(O1)), CC);
    c64 P2 = mni(O2);
    c64 P3 = sclc(subc(mni(O3), O3, NEG1), CC);
    x[0] = addc(E0, O0); x[4] = subc(E0, O0, NEG1);
    x[1] = addc(E1, P1); x[5] = subc(E1, P1, NEG1);
    x[2] = addc(E2, P2); x[6] = subc(E2, P2, NEG1);
    x[3] = addc(E3, P3); x[7] = subc(E3, P3, NEG1);
}

// Twiddle powers w^1..w^7 via depth-3 tree (shared by both rows).
__device__ __forceinline__ void wpowers(float w1r, float w1i, float* wr, float* wi)
{
    wr[1] = w1r; wi[1] = w1i;
    cmul(w1r, w1i, w1r, w1i, wr[2], wi[2]);
    cmul(wr[2], wi[2], w1r, w1i, wr[3], wi[3]);
    cmul(wr[2], wi[2], wr[2], wi[2], wr[4], wi[4]);
    cmul(wr[2], wi[2], wr[3], wi[3], wr[5], wi[5]);
    cmul(wr[3], wi[3], wr[3], wi[3], wr[6], wi[6]);
    cmul(wr[3], wi[3], wr[4], wi[4], wr[7], wi[7]);
}

// Stage<8> specialized per warp-uniform p (compile-time twiddles).
template <int P>
__device__ __forceinline__ void stage8_fixed(c64* zA, c64* zB, int tid,
                                             c64 NEG1, c64 CC)
{
    const int g    = tid & 63;
    const int base = g * 64 + P;
    const int q0   = Sc(base);

    c64 vA[8], vB[8];
    #pragma unroll
    for (int k = 0; k < 8; ++k) {
        int q = q0 ^ Sc(k * 8);
        vA[k] = zA[q];
        vB[k] = zB[q];
    }

    c64 xA[8], xB[8];
    xA[0] = vA[0]; xB[0] = vB[0];
    #pragma unroll
    for (int k = 1; k < 8; ++k) {
        if (P == 0) {
            xA[k] = vA[k];
            xB[k] = vB[k];
        } else {
            const float wr =  C64L(P * k);
            const float wi = -S64L(P * k);
            xA[k] = cmulp(vA[k], wr, wi);
            xB[k] = cmulp(vB[k], wr, wi);
        }
    }
    dft8p(xA, NEG1, CC);
    dft8p(xB, NEG1, CC);
    #pragma unroll
    for (int k = 0; k < 8; ++k) {
        int q = q0 ^ Sc(k * 8);
        zA[q] = xA[k];
        zB[q] = xB[k];
    }
}

// Stage<64>: runtime twiddles via wpowers (p varies within warp).
__device__ __forceinline__ void stage64_2(c64* zA, c64* zB, const float2* T,
                                          int tid, c64 NEG1, c64 CC)
{
    const int p = tid >> 3, g = tid & 7;
    const int base = g * 512 + p;
    const int q0   = Sc(base);

    c64 vA[8], vB[8];
    #pragma unroll
    for (int k = 0; k < 8; ++k) {
        int q = q0 ^ Sc(k * 64);
        vA[k] = zA[q];
        vB[k] = zB[q];
    }

    const float2 w1 = T[p * 16];
    float wr[8], wi[8];
    wpowers(w1.x, w1.y, wr, wi);

    c64 xA[8], xB[8];
    xA[0] = vA[0]; xB[0] = vB[0];
    #pragma unroll
    for (int k = 1; k < 8; ++k) {
        xA[k] = cmulp(vA[k], wr[k], wi[k]);
        xB[k] = cmulp(vB[k], wr[k], wi[k]);
    }
    dft8p(xA, NEG1, CC);
    dft8p(xB, NEG1, CC);
    #pragma unroll
    for (int k = 0; k < 8; ++k) {
        int q = q0 ^ Sc(k * 64);
        zA[q] = xA[k];
        zB[q] = xB[k];
    }
}

__global__ void __launch_bounds__(THREADS, 2) snr_fft_kernel(
    const float* __restrict__ outputs,
    const float* __restrict__ targets,
    float* __restrict__ d_out)
{
    extern __shared__ float smem_raw[];
    char* sb = reinterpret_cast<char*>(smem_raw);
    c64*    zA = reinterpret_cast<c64*>(sb + ZA_OFF);    // 4096 c64
    c64*    zB = reinterpret_cast<c64*>(sb + ZB_OFF);    // 4096 c64
    float2* T  = reinterpret_cast<float2*>(sb + T_OFF);  // 1032 float2

    const int tid = threadIdx.x;
    const int rowA = 2 * blockIdx.x;
    const uint32_t mbar = smem_u32(sb + MBAR_OFF);

    const c64 NEG1 = 0xBF800000BF800000ULL;              // (-1.0f, -1.0f)
    const c64 CC   = pk(0.70710678118654752f, 0.70710678118654752f);

    // Hoist targets (used late; pull latency to the front).
    const float tgtA = targets[rowA];
    const float tgtB = targets[rowA + 1];

    // Async bulk copy of the twiddle table (overlaps row loads + stage 1).
    if (tid == 0) {
        asm volatile("mbarrier.init.shared.b64 [%0], 1;" :: "r"(mbar) : "memory");
        asm volatile("mbarrier.arrive.expect_tx.shared.b64 _, [%0], %1;"
                     :: "r"(mbar), "r"((uint32_t)TAB_BYTES) : "memory");
        asm volatile("cp.async.bulk.shared::cluster.global.mbarrier::complete_tx::bytes "
                     "[%0], [%1], %2, [%3];"
                     :: "r"(smem_u32(T)), "l"((const void*)g_tab),
                        "r"((uint32_t)TAB_BYTES), "r"(mbar) : "memory");
    }

    // Fused coalesced load + stage 1 for BOTH rows (16 LDG.64, MLP=16).
    {
        const c64* xrA = reinterpret_cast<const c64*>(outputs) + (size_t)rowA * M_FFT;
        const c64* xrB = xrA + M_FFT;
        c64 a[8], b[8];
        #pragma unroll
        for (int k = 0; k < 8; ++k) {
            a[k] = xrA[tid + (k << 9)];
            b[k] = xrB[tid + (k << 9)];
        }

        // L2 prefetch for the CTA one wave ahead (64KB = 512 x 128B lines).
        // Issued after demand loads so it never delays them; converts the
        // next wave's DRAM-latency LDGs into L2 hits.
        {
            int pf = blockIdx.x + WAVE_CTAS;
            if (pf < GRID_CTAS) {
                const char* np = reinterpret_cast<const char*>(
                    outputs + (size_t)(2 * pf) * N_LEN) + tid * 128;
                asm volatile("prefetch.global.L2 [%0];" :: "l"(np));
            }
        }

        dft8p(a, NEG1, CC);
        dft8p(b, NEG1, CC);
        const int t8 = ((tid & 7) << 6) | (((tid >> 3) & 7) << 3) | (tid >> 6);
        const int q0 = Sc(t8 << 3);
        #pragma unroll
        for (int k = 0; k < 8; ++k) {      // Sc(k) = k for k < 8
            zA[q0 ^ k] = a[k];
            zB[q0 ^ k] = b[k];
        }
    }
    __syncthreads();     // stage-1 data published; also orders mbar init

    // Stage <8>: warp-uniform p = tid>>6 -> compile-time twiddles.
    switch (tid >> 6) {
        case 0: stage8_fixed<0>(zA, zB, tid, NEG1, CC); break;
        case 1: stage8_fixed<1>(zA, zB, tid, NEG1, CC); break;
        case 2: stage8_fixed<2>(zA, zB, tid, NEG1, CC); break;
        case 3: stage8_fixed<3>(zA, zB, tid, NEG1, CC); break;
        case 4: stage8_fixed<4>(zA, zB, tid, NEG1, CC); break;
        case 5: stage8_fixed<5>(zA, zB, tid, NEG1, CC); break;
        case 6: stage8_fixed<6>(zA, zB, tid, NEG1, CC); break;
        default: stage8_fixed<7>(zA, zB, tid, NEG1, CC); break;
    }
    __syncthreads();

    // Wait for the table before first T use (stage<64>).
    asm volatile(
        "{\n\t.reg .pred P;\n"
        "WAITL%=:\n\t"
        "mbarrier.try_wait.parity.acquire.cta.shared::cta.b64 P, [%0], 0;\n\t"
        "@!P bra WAITL%=;\n\t}"
        :: "r"(mbar) : "memory");

    stage64_2(zA, zB, T, tid, NEG1, CC);
    __syncthreads();

    // Stage L=512: load BOTH rows first, then compute.
    c64 bA[4], bB[4];
    {
        const int q0 = Sc(tid);
        c64 vA[8], vB[8];
        #pragma unroll
        for (int k = 0; k < 8; ++k) {
            int q = q0 ^ Sc(k * 512);
            vA[k] = zA[q];
            vB[k] = zB[q];
        }

        const float2 w1 = T[2 * tid];      // exp(-2*pi*i*tid/4096)
        float wr[8], wi[8];
        wpowers(w1.x, w1.y, wr, wi);

        c64 xA[8], xB[8];
        xA[0] = vA[0]; xB[0] = vB[0];
        #pragma unroll
        for (int k = 1; k < 8; ++k) {
            xA[k] = cmulp(vA[k], wr[k], wi[k]);
            xB[k] = cmulp(vB[k], wr[k], wi[k]);
        }
        dft8p(xA, NEG1, CC);
        dft8p(xB, NEG1, CC);

        // Publish only the index range the epilogue reads: [272, 3824].
        #pragma unroll
        for (int k = 0; k < 8; ++k) {
            bool need = (k == 0) ? (tid >= 272)
                      : (k == 7) ? (tid <= 240)
                      : true;
            if (need) {
                int q = q0 ^ Sc(k * 512);
                zA[q] = xA[k];
                zB[q] = xB[k];
            }
        }
        #pragma unroll
        for (int k = 0; k < 4; ++k) { bA[k] = xA[k]; bB[k] = xB[k]; }
    }
    __syncthreads();     // final Z published for both rows

    // Weight-free band sums over k in [273, 1706] for both rows.
    // Unpack twiddle folded: W(tid + 512c) = T[tid] * exp(-i*pi*c/8).
    const float2 Wt = T[tid];
    const float ecr[4] = { 1.0f, 0.92387953251128675613f,
                           0.70710678118654752440f, 0.38268343236508977173f };
    const float eci[4] = { 0.0f, -0.38268343236508977173f,
                          -0.70710678118654752440f, -0.92387953251128675613f };
    float bandA0 = 0.0f, bandA1 = 0.0f, bandB0 = 0.0f, bandB1 = 0.0f;
    #pragma unroll
    for (int c = 0; c < 4; ++c) {
        int k = tid + (c << 9);
        bool valid = (c == 1) || (c == 2) ||
                     (c == 0 ? (tid >= MIN_IDX) : (k <= MAX_IDX - 1));
        if (valid) {
            float Wr, Wi;
            if (c == 0) { Wr = Wt.x; Wi = Wt.y; }
            else        { cmul(Wt.x, Wt.y, ecr[c], eci[c], Wr, Wi); }
            int q2 = Sc(M_FFT - k);
            {   // row A
                c64 Z2p = zA[q2];
                float Z2r = lof(Z2p), Z2i = hif(Z2p);
                float xrc = lof(bA[c]), xic = hif(bA[c]);
                float Er = 0.5f * (xrc + Z2r);
                float Ei = 0.5f * (xic - Z2i);
                float Or = 0.5f * (xic + Z2i);
                float Oi = 0.5f * (Z2r - xrc);
                float Xr = Er + Wr * Or - Wi * Oi;
                float Xi = Ei + Wr * Oi + Wi * Or;
                float pw = (Xr * Xr + Xi * Xi) * (1.0f / (float)N_LEN);
                if (c & 1) bandA1 += pw; else bandA0 += pw;
            }
            {   // row B
                c64 Z2p = zB[q2];
                float Z2r = lof(Z2p), Z2i = hif(Z2p);
                float xrc = lof(bB[c]), xic = hif(bB[c]);
                float Er = 0.5f * (xrc + Z2r);
                float Ei = 0.5f * (xic - Z2i);
                float Or = 0.5f * (xic + Z2i);
                float Oi = 0.5f * (Z2r - xrc);
                float Xr = Er + Wr * Or - Wi * Oi;
                float Xi = Ei + Wr * Oi + Wi * Or;
                float pw = (Xr * Xr + Xi * Xi) * (1.0f / (float)N_LEN);
                if (c & 1) bandB1 += pw; else bandB0 += pw;
            }
        }
    }
    float bandA = bandA0 + bandA1;
    float bandB = bandB0 + bandB1;

    // Special bins: threads 0..5 do row A, threads 8..13 do row B.
    float spec_sig = 0.0f, spec_corr = 0.0f;
    bool isSpec = (tid < 6) || (tid >= 8 && tid < 14);
    if (isSpec) {
        bool isB = tid >= 8;
        int s = isB ? tid - 8 : tid;
        const int   joff[6] = { -1, 0, 1, -1, 0, 1 };
        const float uw[6]   = { 0.5f, 1.0f, 0.5f, 0.0f, 1.0f, 0.0f };
        const float mw[6]   = { 0.5f, 1.0f, 0.5f, 1.0f, 1.0f, 1.0f };
        const float tgt = isB ? tgtB : tgtA;
        int ib = (int)floorf(tgt / DF) - 1;
        if (ib < 0) ib = 0;
        if (ib > M_FFT - 3) ib = M_FFT - 3;
        int r = ib;
        float best = fabsf((float)ib * DF - tgt);
        #pragma unroll
        for (int i = 1; i <= 3; ++i) {
            float d = fabsf((float)(ib + i) * DF - tgt);
            if (d < best) { best = d; r = ib + i; }
        }
        int j = (s < 3 ? r : 2 * r) + joff[s];
        const c64* zp = isB ? zB : zA;
        c64 Z1p = zp[Sc(j)];
        c64 Z2p = zp[Sc(M_FFT - j)];
        float Z1r = lof(Z1p), Z1i = hif(Z1p);
        float Z2r = lof(Z2p), Z2i = hif(Z2p);
        float Er = 0.5f * (Z1r + Z2r);
        float Ei = 0.5f * (Z1i - Z2i);
        float Or = 0.5f * (Z1i + Z2i);
        float Oi = 0.5f * (Z2r - Z1r);
        float Ws, Wc;
        sincospif(-(float)j * (1.0f / 4096.0f), &Ws, &Wc);
        float Xr = Er + Wc * Or - Ws * Oi;
        float Xi = Ei + Wc * Oi + Ws * Or;
        float P = (Xr * Xr + Xi * Xi) * (1.0f / (float)N_LEN);
        spec_sig  = uw[s] * P;
        spec_corr = (j >= MIN_IDX && j < MAX_IDX) ? mw[s] * P : 0.0f;
    }

    // Band reductions (both rows) within warps.
    #pragma unroll
    for (int o = 16; o > 0; o >>= 1) {
        bandA += __shfl_down_sync(0xffffffffu, bandA, o);
        bandB += __shfl_down_sync(0xffffffffu, bandB, o);
    }
    const int wid = tid >> 5, lane = tid & 31;
    float* red = reinterpret_cast<float*>(T);   // T reads done after this barrier
    __syncthreads();
    if (lane == 0) { red[wid] = bandA; red[16 + wid] = bandB; }
    if (isSpec) {
        bool isB = tid >= 8;
        int s = isB ? tid - 8 : tid;
        int off = isB ? 44 : 32;
        red[off + s]     = spec_sig;
        red[off + 6 + s] = spec_corr;
    }
    __syncthreads();

    __shared__ bool is_last;
    if (tid < 2) {
        int boff = tid ? 16 : 0;
        int soff = tid ? 44 : 32;
        float Bt = 0.0f;
        #pragma unroll
        for (int i = 0; i < 16; ++i) Bt += red[boff + i];
        float Sg = 0.0f, Cr = 0.0f;
        #pragma unroll
        for (int i = 0; i < 6; ++i) { Sg += red[soff + i]; Cr += red[soff + 6 + i]; }
        g_losses[rowA + tid] = -10.0f * log10f(Sg / ((Bt - Cr) + 1.0f));
        __threadfence();
    }
    __syncthreads();
    if (tid == 0) {
        unsigned int old = atomicAdd(&g_ctr, 1u);
        is_last = (old == (unsigned int)(GRID_CTAS - 1));
    }
    __syncthreads();

    // Last CTA computes the mean (fixed-order, deterministic), resets ctr.
    if (is_last) {
        float s = 0.0f;
        for (int i = tid; i < B_ROWS; i += THREADS) s += g_losses[i];
        #pragma unroll
        for (int o = 16; o > 0; o >>= 1) s += __shfl_down_sync(0xffffffffu, s, o);
        __syncthreads();
        if (lane == 0) red[wid] = s;
        __syncthreads();
        if (tid == 0) {
            float t = 0.0f;
            #pragma unroll
            for (int i = 0; i < 16; ++i) t += red[i];
            d_out[0] = t * (1.0f / (float)B_ROWS);
            g_ctr = 0;
        }
    }
}

extern "C" void kernel_launch(void* const* d_in, const int* in_sizes, int n_in,
                              void* d_out, int out_size)
{
    const float* outputs = (const float*)d_in[0];   // [4096, 8192] f32
    const float* targets = (const float*)d_in[1];   // [4096, 1]    f32
    (void)in_sizes; (void)n_in; (void)out_size;

    cudaFuncSetAttribute(snr_fft_kernel,
                         cudaFuncAttributeMaxDynamicSharedMemorySize, SMEM_TOTAL);

    twiddle_init_kernel<<<3, 512>>>();
    snr_fft_kernel<<<GRID_CTAS, THREADS, SMEM_TOTAL>>>(outputs, targets, (float*)d_out);
}